// round 4
// baseline (speedup 1.0000x reference)
#include <cuda_runtime.h>
#include <cuda_bf16.h>
#include <math.h>

// ---------------------------------------------------------------------------
// SelfAttention: out = softmax((x Wq^T * 0.06)(x Wk^T)^T) * dropmask @ (x Wv^T) @ Wo^T
// N = 8192 frames, M = 1024 features. All fp32.
// Baseline: fp32 SIMT SGEMM (128x128x8 tiles, 8x8 per thread). Compute-bound
// at the FFMA roofline; tensor-core (tcgen05) migration comes next round.
// ---------------------------------------------------------------------------

#define NF 8192
#define MF 1024

// Scratch (allocation-free rule: __device__ globals)
__device__ float g_K[(size_t)NF * MF];   // 32 MB
__device__ float g_Q[(size_t)NF * MF];   // 32 MB
__device__ float g_V[(size_t)NF * MF];   // 32 MB
__device__ float g_Y[(size_t)NF * MF];   // 32 MB
__device__ float g_S[(size_t)NF * NF];   // 256 MB (logits / attn weights)

#define BM 128
#define BN 128
#define BK 8
#define SPAD 4   // smem row padding (floats) to break store-bank conflicts

// ---------------------------------------------------------------------------
// NT GEMM: C[Mrows x Ncols] = alpha * A[Mrows x Kdim] * B[Ncols x Kdim]^T
// (both operands K-major / row-major). Dims assumed multiples of 128 / BK.
// ---------------------------------------------------------------------------
__global__ __launch_bounds__(256, 2)
void gemm_nt(const float* __restrict__ A, const float* __restrict__ B,
             float* __restrict__ C, int Mrows, int Ncols, int Kdim, float alpha)
{
    __shared__ float As[BK][BM + SPAD];
    __shared__ float Bs[BK][BN + SPAD];

    const int tid = threadIdx.x;
    const int tx  = tid & 15;    // 0..15 -> column groups
    const int ty  = tid >> 4;    // 0..15 -> row groups

    const float* Ablk = A + (size_t)blockIdx.y * BM * Kdim;
    const float* Bblk = B + (size_t)blockIdx.x * BN * Kdim;
    float*       Cblk = C + (size_t)blockIdx.y * BM * Ncols + (size_t)blockIdx.x * BN;

    // Loader mapping: each thread brings one float4 of A and one of B per k-tile
    const int lrow = tid >> 1;         // 0..127
    const int lk4  = (tid & 1) * 4;    // 0 or 4

    float acc[8][8];
    #pragma unroll
    for (int i = 0; i < 8; i++)
        #pragma unroll
        for (int j = 0; j < 8; j++) acc[i][j] = 0.0f;

    for (int k0 = 0; k0 < Kdim; k0 += BK) {
        float4 av = *(const float4*)(Ablk + (size_t)lrow * Kdim + k0 + lk4);
        float4 bv = *(const float4*)(Bblk + (size_t)lrow * Kdim + k0 + lk4);
        As[lk4 + 0][lrow] = av.x; As[lk4 + 1][lrow] = av.y;
        As[lk4 + 2][lrow] = av.z; As[lk4 + 3][lrow] = av.w;
        Bs[lk4 + 0][lrow] = bv.x; Bs[lk4 + 1][lrow] = bv.y;
        Bs[lk4 + 2][lrow] = bv.z; Bs[lk4 + 3][lrow] = bv.w;
        __syncthreads();

        #pragma unroll
        for (int k = 0; k < BK; k++) {
            float4 a0 = *(const float4*)&As[k][ty * 4];
            float4 a1 = *(const float4*)&As[k][64 + ty * 4];
            float4 b0 = *(const float4*)&Bs[k][tx * 4];
            float4 b1 = *(const float4*)&Bs[k][64 + tx * 4];
            float a[8] = {a0.x, a0.y, a0.z, a0.w, a1.x, a1.y, a1.z, a1.w};
            float b[8] = {b0.x, b0.y, b0.z, b0.w, b1.x, b1.y, b1.z, b1.w};
            #pragma unroll
            for (int i = 0; i < 8; i++)
                #pragma unroll
                for (int j = 0; j < 8; j++)
                    acc[i][j] = fmaf(a[i], b[j], acc[i][j]);
        }
        __syncthreads();
    }

    #pragma unroll
    for (int ih = 0; ih < 2; ih++) {
        #pragma unroll
        for (int i = 0; i < 4; i++) {
            int r = ih * 64 + ty * 4 + i;
            float* crow = Cblk + (size_t)r * Ncols;
            int ai = ih * 4 + i;
            float4 v0 = make_float4(alpha * acc[ai][0], alpha * acc[ai][1],
                                    alpha * acc[ai][2], alpha * acc[ai][3]);
            float4 v1 = make_float4(alpha * acc[ai][4], alpha * acc[ai][5],
                                    alpha * acc[ai][6], alpha * acc[ai][7]);
            *(float4*)(crow + tx * 4)      = v0;
            *(float4*)(crow + 64 + tx * 4) = v1;
        }
    }
}

// ---------------------------------------------------------------------------
// NN GEMM: C[Mrows x Ncols] = A[Mrows x Kdim] * B[Kdim x Ncols]  (row-major)
// ---------------------------------------------------------------------------
__global__ __launch_bounds__(256, 2)
void gemm_nn(const float* __restrict__ A, const float* __restrict__ B,
             float* __restrict__ C, int Mrows, int Ncols, int Kdim)
{
    __shared__ float As[BK][BM + SPAD];
    __shared__ float Bs[BK][BN + SPAD];

    const int tid = threadIdx.x;
    const int tx  = tid & 15;
    const int ty  = tid >> 4;

    const float* Ablk = A + (size_t)blockIdx.y * BM * Kdim;
    const float* Bblk = B + (size_t)blockIdx.x * BN;
    float*       Cblk = C + (size_t)blockIdx.y * BM * Ncols + (size_t)blockIdx.x * BN;

    const int larow = tid >> 1;        // A loader: row 0..127
    const int lak4  = (tid & 1) * 4;   // A loader: k 0 or 4
    const int lbk   = tid >> 5;        // B loader: k 0..7
    const int lbn4  = (tid & 31) * 4;  // B loader: n 0..124

    float acc[8][8];
    #pragma unroll
    for (int i = 0; i < 8; i++)
        #pragma unroll
        for (int j = 0; j < 8; j++) acc[i][j] = 0.0f;

    for (int k0 = 0; k0 < Kdim; k0 += BK) {
        float4 av = *(const float4*)(Ablk + (size_t)larow * Kdim + k0 + lak4);
        float4 bv = *(const float4*)(Bblk + (size_t)(k0 + lbk) * Ncols + lbn4);
        As[lak4 + 0][larow] = av.x; As[lak4 + 1][larow] = av.y;
        As[lak4 + 2][larow] = av.z; As[lak4 + 3][larow] = av.w;
        *(float4*)&Bs[lbk][lbn4] = bv;
        __syncthreads();

        #pragma unroll
        for (int k = 0; k < BK; k++) {
            float4 a0 = *(const float4*)&As[k][ty * 4];
            float4 a1 = *(const float4*)&As[k][64 + ty * 4];
            float4 b0 = *(const float4*)&Bs[k][tx * 4];
            float4 b1 = *(const float4*)&Bs[k][64 + tx * 4];
            float a[8] = {a0.x, a0.y, a0.z, a0.w, a1.x, a1.y, a1.z, a1.w};
            float b[8] = {b0.x, b0.y, b0.z, b0.w, b1.x, b1.y, b1.z, b1.w};
            #pragma unroll
            for (int i = 0; i < 8; i++)
                #pragma unroll
                for (int j = 0; j < 8; j++)
                    acc[i][j] = fmaf(a[i], b[j], acc[i][j]);
        }
        __syncthreads();
    }

    #pragma unroll
    for (int ih = 0; ih < 2; ih++) {
        #pragma unroll
        for (int i = 0; i < 4; i++) {
            int r = ih * 64 + ty * 4 + i;
            float* crow = Cblk + (size_t)r * Ncols;
            int ai = ih * 4 + i;
            float4 v0 = make_float4(acc[ai][0], acc[ai][1], acc[ai][2], acc[ai][3]);
            float4 v1 = make_float4(acc[ai][4], acc[ai][5], acc[ai][6], acc[ai][7]);
            *(float4*)(crow + tx * 4)      = v0;
            *(float4*)(crow + 64 + tx * 4) = v1;
        }
    }
}

// ---------------------------------------------------------------------------
// Fused softmax (row-wise) + dropout mask: S[r,:] = softmax(S[r,:]) * keep
// keep = (u >= 0.5) ? 2 : 0.   One block per row; row (32 KB) held in smem.
// ---------------------------------------------------------------------------
__global__ __launch_bounds__(256)
void softmax_dropout(float* __restrict__ S, const float* __restrict__ u, int Ncols)
{
    __shared__ float row[NF];
    __shared__ float red[256];

    const int r   = blockIdx.x;
    const int tid = threadIdx.x;
    float* Srow = S + (size_t)r * Ncols;
    const float* urow = u + (size_t)r * Ncols;

    float lmax = -INFINITY;
    for (int c = tid; c < Ncols; c += 256) {
        float v = Srow[c];
        row[c] = v;
        lmax = fmaxf(lmax, v);
    }
    red[tid] = lmax;
    __syncthreads();
    #pragma unroll
    for (int s = 128; s > 0; s >>= 1) {
        if (tid < s) red[tid] = fmaxf(red[tid], red[tid + s]);
        __syncthreads();
    }
    const float m = red[0];
    __syncthreads();

    float lsum = 0.0f;
    for (int c = tid; c < Ncols; c += 256) {
        float e = __expf(row[c] - m);
        row[c] = e;
        lsum += e;
    }
    red[tid] = lsum;
    __syncthreads();
    #pragma unroll
    for (int s = 128; s > 0; s >>= 1) {
        if (tid < s) red[tid] += red[tid + s];
        __syncthreads();
    }
    const float inv = 1.0f / red[0];

    for (int c = tid; c < Ncols; c += 256) {
        float keep = (urow[c] >= 0.5f) ? 2.0f : 0.0f;
        Srow[c] = row[c] * inv * keep;
    }
}

// ---------------------------------------------------------------------------
// Launch
// ---------------------------------------------------------------------------
extern "C" void kernel_launch(void* const* d_in, const int* in_sizes, int n_in,
                              void* d_out, int out_size)
{
    const float* x  = (const float*)d_in[0];
    const float* Wk = (const float*)d_in[1];
    const float* Wq = (const float*)d_in[2];
    const float* Wv = (const float*)d_in[3];
    const float* Wo = (const float*)d_in[4];
    const float* u  = (const float*)d_in[5];
    float* out = (float*)d_out;

    float *K, *Q, *V, *S, *Y;
    cudaGetSymbolAddress((void**)&K, g_K);
    cudaGetSymbolAddress((void**)&Q, g_Q);
    cudaGetSymbolAddress((void**)&V, g_V);
    cudaGetSymbolAddress((void**)&S, g_S);
    cudaGetSymbolAddress((void**)&Y, g_Y);

    const dim3 blk(256);
    const dim3 gProj(MF / BN, NF / BM);   // (8, 64)
    const dim3 gAttn(NF / BN, NF / BM);   // (64, 64)

    // Projections: K = x Wk^T, Q = 0.06 * x Wq^T, V = x Wv^T
    gemm_nt<<<gProj, blk>>>(x, Wk, K, NF, MF, MF, 1.0f);
    gemm_nt<<<gProj, blk>>>(x, Wq, Q, NF, MF, MF, 0.06f);
    gemm_nt<<<gProj, blk>>>(x, Wv, V, NF, MF, MF, 1.0f);

    // Logits: S = Q K^T
    gemm_nt<<<gAttn, blk>>>(Q, K, S, NF, NF, MF, 1.0f);

    // S = softmax(S) * dropout mask (in place)
    softmax_dropout<<<NF, blk>>>(S, u, NF);

    // Y = S V
    gemm_nn<<<gProj, blk>>>(S, V, Y, NF, MF, NF);

    // out = Y Wo^T
    gemm_nt<<<gProj, blk>>>(Y, Wo, out, NF, MF, MF, 1.0f);
}

// round 6
// speedup vs baseline: 2.1984x; 2.1984x over previous
#include <cuda_runtime.h>
#include <cuda_bf16.h>
#include <cstdint>
#include <math.h>

// ---------------------------------------------------------------------------
// SelfAttention via split-bf16 HMMA (mma.sync m16n8k16, valid on sm_103 base).
// out = softmax((x Wq^T * 0.06)(x Wk^T)^T)*dropmask @ (x Wv^T) @ Wo^T
// N = 8192, M = 1024. fp32-accurate: C = Ah*Bh + Ah*Bl + Al*Bh (fp32 acc).
// ---------------------------------------------------------------------------

#define NF 8192
#define MF 1024

// ---------------- scratch (__device__ globals; no allocation allowed) ------
__device__ float         g_S [(size_t)NF * NF];                 // 256 MB logits
__device__ __nv_bfloat16 g_Sh[(size_t)NF * NF];                 // 128 MB
__device__ __nv_bfloat16 g_Sl[(size_t)NF * NF];                 // 128 MB
__device__ __nv_bfloat16 g_xh[(size_t)NF * MF], g_xl[(size_t)NF * MF];
__device__ __nv_bfloat16 g_Wkh[(size_t)MF * MF], g_Wkl[(size_t)MF * MF];
__device__ __nv_bfloat16 g_Wqh[(size_t)MF * MF], g_Wql[(size_t)MF * MF];
__device__ __nv_bfloat16 g_Wvh[(size_t)MF * MF], g_Wvl[(size_t)MF * MF];
__device__ __nv_bfloat16 g_Woh[(size_t)MF * MF], g_Wol[(size_t)MF * MF];
__device__ __nv_bfloat16 g_Kh[(size_t)NF * MF], g_Kl[(size_t)NF * MF];
__device__ __nv_bfloat16 g_Qh[(size_t)NF * MF], g_Ql[(size_t)NF * MF];
__device__ __nv_bfloat16 g_Vth[(size_t)MF * NF], g_Vtl[(size_t)MF * NF]; // V^T
__device__ __nv_bfloat16 g_Yh[(size_t)NF * MF], g_Yl[(size_t)NF * MF];

// ---------------- tile config ----------------------------------------------
#define BM 128
#define BN 128
#define BKE 32                    // K elems per chunk (bf16)
#define RS 40                     // smem row stride in elems (padded: 80B)
#define TILE_B (BM * RS * 2)      // 10240 bytes per operand tile
#define OFF_AH 0
#define OFF_AL (TILE_B)
#define OFF_BH (2 * TILE_B)
#define OFF_BL (3 * TILE_B)
#define STAGE_B (4 * TILE_B)      // 40960
#define DYN_SMEM (2 * STAGE_B)    // 81920

// ---------------- PTX helpers ----------------------------------------------
__device__ __forceinline__ uint32_t s2u(const void* p) {
    uint32_t a;
    asm("{ .reg .u64 t; cvta.to.shared.u64 t, %1; cvt.u32.u64 %0, t; }"
        : "=r"(a) : "l"(p));
    return a;
}
__device__ __forceinline__ void cpa16(uint32_t dst, const void* src) {
    asm volatile("cp.async.cg.shared.global [%0], [%1], 16;"
                 :: "r"(dst), "l"(src) : "memory");
}
__device__ __forceinline__ void ldsm4(uint32_t* r, uint32_t addr) {
    asm volatile("ldmatrix.sync.aligned.m8n8.x4.shared.b16 {%0,%1,%2,%3}, [%4];"
                 : "=r"(r[0]), "=r"(r[1]), "=r"(r[2]), "=r"(r[3]) : "r"(addr));
}
__device__ __forceinline__ void mma16816(float* c, const uint32_t* a,
                                         const uint32_t* b) {
    asm volatile(
        "mma.sync.aligned.m16n8k16.row.col.f32.bf16.bf16.f32 "
        "{%0,%1,%2,%3}, {%4,%5,%6,%7}, {%8,%9}, {%0,%1,%2,%3};"
        : "+f"(c[0]), "+f"(c[1]), "+f"(c[2]), "+f"(c[3])
        : "r"(a[0]), "r"(a[1]), "r"(a[2]), "r"(a[3]), "r"(b[0]), "r"(b[1]));
}
__device__ __forceinline__ void split2(float v, __nv_bfloat16& h, __nv_bfloat16& l) {
    h = __float2bfloat16(v);
    l = __float2bfloat16(v - __bfloat162float(h));
}

// ---------------------------------------------------------------------------
// Split-bf16 NT GEMM: C[M,N] = alpha * (Ah+Al)[M,K] * ((Bh+Bl)[N,K])^T
// mode 0: fp32 out (Cf). mode 1: split bf16 out (Ch, Cl).
// mode 2: split bf16 TRANSPOSED out: Ch[col * Mrows + row] (for V^T).
// Requires M,N mult of 128; K mult of 32.
// ---------------------------------------------------------------------------
__global__ __launch_bounds__(256, 1)
void gemm_mma(const __nv_bfloat16* __restrict__ Ah, const __nv_bfloat16* __restrict__ Al,
              const __nv_bfloat16* __restrict__ Bh, const __nv_bfloat16* __restrict__ Bl,
              float* __restrict__ Cf,
              __nv_bfloat16* __restrict__ Ch, __nv_bfloat16* __restrict__ Cl,
              int Mrows, int Ncols, int Kdim, float alpha, int mode)
{
    extern __shared__ char dynraw[];
    const uint32_t sbase = s2u(dynraw);

    const int tid  = threadIdx.x;
    const int wid  = tid >> 5;
    const int lane = tid & 31;
    const int bx = blockIdx.x, by = blockIdx.y;

    const int wm = wid >> 2;            // 0..1  (M): warp M origin = wm*64
    const int wn = wid & 3;             // 0..3  (N): warp N origin = wn*32
    const int wmBase = wm * 64;
    const int wnBase = wn * 32;

    const size_t rowA0 = (size_t)by * BM;
    const size_t rowB0 = (size_t)bx * BN;

    // loader: one 32-K chunk of all four operand tiles (16B per cp.async)
    auto load_chunk = [&](int kc, int buf) {
        const int k0 = kc * BKE;
        const uint32_t sb = sbase + buf * STAGE_B;
        #pragma unroll
        for (int i = 0; i < 2; i++) {
            const int idx = tid + i * 256;          // 0..511
            const int r = idx >> 2, c = idx & 3;    // r:0..127, c:0..3
            const uint32_t so = (uint32_t)(r * RS * 2 + c * 16);
            const size_t ga = (rowA0 + r) * (size_t)Kdim + k0 + c * 8;
            const size_t gb = (rowB0 + r) * (size_t)Kdim + k0 + c * 8;
            cpa16(sb + OFF_AH + so, Ah + ga);
            cpa16(sb + OFF_AL + so, Al + ga);
            cpa16(sb + OFF_BH + so, Bh + gb);
            cpa16(sb + OFF_BL + so, Bl + gb);
        }
        asm volatile("cp.async.commit_group;" ::: "memory");
    };

    float acc[4][4][4];
    #pragma unroll
    for (int i = 0; i < 4; i++)
        #pragma unroll
        for (int j = 0; j < 4; j++)
            #pragma unroll
            for (int k = 0; k < 4; k++) acc[i][j][k] = 0.0f;

    const int nchunks = Kdim / BKE;
    load_chunk(0, 0);

    // per-lane ldmatrix row/col components (q = matrix index group)
    const int q  = lane >> 3;           // 0..3
    const int r8 = lane & 7;
    const int aRowOff = ((q & 1) ? 8 : 0) + r8;   // A: q&1 -> +8 rows
    const int aKOff   = ((q >> 1) ? 8 : 0);       // A: q>>1 -> +8 k
    const int bRowOff = ((q >> 1) ? 8 : 0) + r8;  // B: q>>1 -> +8 n rows
    const int bKOff   = ((q & 1) ? 8 : 0);        // B: q&1 -> +8 k

    int buf = 0;
    for (int kc = 0; kc < nchunks; kc++) {
        if (kc + 1 < nchunks) {
            load_chunk(kc + 1, 1 - buf);
            asm volatile("cp.async.wait_group 1;" ::: "memory");
        } else {
            asm volatile("cp.async.wait_group 0;" ::: "memory");
        }
        __syncthreads();

        const uint32_t sb = sbase + buf * STAGE_B;
        #pragma unroll
        for (int ks = 0; ks < 2; ks++) {
            uint32_t ah[4][4], alr[4][4], bh[4][2], blr[4][2];
            #pragma unroll
            for (int am = 0; am < 4; am++) {
                const uint32_t off =
                    (uint32_t)((wmBase + am * 16 + aRowOff) * RS
                               + ks * 16 + aKOff) * 2;
                ldsm4(ah[am],  sb + OFF_AH + off);
                ldsm4(alr[am], sb + OFF_AL + off);
            }
            #pragma unroll
            for (int j = 0; j < 2; j++) {
                const uint32_t off =
                    (uint32_t)((wnBase + j * 16 + bRowOff) * RS
                               + ks * 16 + bKOff) * 2;
                uint32_t t[4];
                ldsm4(t, sb + OFF_BH + off);
                bh[j * 2][0] = t[0]; bh[j * 2][1] = t[1];
                bh[j * 2 + 1][0] = t[2]; bh[j * 2 + 1][1] = t[3];
                ldsm4(t, sb + OFF_BL + off);
                blr[j * 2][0] = t[0]; blr[j * 2][1] = t[1];
                blr[j * 2 + 1][0] = t[2]; blr[j * 2 + 1][1] = t[3];
            }
            #pragma unroll
            for (int am = 0; am < 4; am++)
                #pragma unroll
                for (int an = 0; an < 4; an++) {
                    mma16816(acc[am][an], ah[am],  bh[an]);
                    mma16816(acc[am][an], ah[am],  blr[an]);
                    mma16816(acc[am][an], alr[am], bh[an]);
                }
        }
        __syncthreads();
        buf ^= 1;
    }

    // ---------------- epilogue --------------------------------------------
    #pragma unroll
    for (int am = 0; am < 4; am++) {
        const int r0 = by * BM + wmBase + am * 16 + (lane >> 2);
        #pragma unroll
        for (int an = 0; an < 4; an++) {
            const int c0 = bx * BN + wnBase + an * 8 + (lane & 3) * 2;
            const float v00 = alpha * acc[am][an][0];
            const float v01 = alpha * acc[am][an][1];
            const float v10 = alpha * acc[am][an][2];
            const float v11 = alpha * acc[am][an][3];
            if (mode == 0) {
                *(float2*)(Cf + (size_t)r0 * Ncols + c0)       = make_float2(v00, v01);
                *(float2*)(Cf + (size_t)(r0 + 8) * Ncols + c0) = make_float2(v10, v11);
            } else if (mode == 1) {
                __nv_bfloat16 h0, l0, h1, l1;
                split2(v00, h0, l0); split2(v01, h1, l1);
                __nv_bfloat162 hp; hp.x = h0; hp.y = h1;
                __nv_bfloat162 lp; lp.x = l0; lp.y = l1;
                *(__nv_bfloat162*)(Ch + (size_t)r0 * Ncols + c0) = hp;
                *(__nv_bfloat162*)(Cl + (size_t)r0 * Ncols + c0) = lp;
                split2(v10, h0, l0); split2(v11, h1, l1);
                hp.x = h0; hp.y = h1; lp.x = l0; lp.y = l1;
                *(__nv_bfloat162*)(Ch + (size_t)(r0 + 8) * Ncols + c0) = hp;
                *(__nv_bfloat162*)(Cl + (size_t)(r0 + 8) * Ncols + c0) = lp;
            } else {                     // transposed split (V^T)
                __nv_bfloat16 h, l;
                split2(v00, h, l);
                Ch[(size_t)c0 * Mrows + r0] = h;       Cl[(size_t)c0 * Mrows + r0] = l;
                split2(v01, h, l);
                Ch[(size_t)(c0 + 1) * Mrows + r0] = h; Cl[(size_t)(c0 + 1) * Mrows + r0] = l;
                split2(v10, h, l);
                Ch[(size_t)c0 * Mrows + r0 + 8] = h;   Cl[(size_t)c0 * Mrows + r0 + 8] = l;
                split2(v11, h, l);
                Ch[(size_t)(c0 + 1) * Mrows + r0 + 8] = h;
                Cl[(size_t)(c0 + 1) * Mrows + r0 + 8] = l;
            }
        }
    }
}

// ---------------------------------------------------------------------------
// fp32 -> (hi, lo) bf16 split
// ---------------------------------------------------------------------------
__global__ __launch_bounds__(256)
void split_f32(const float* __restrict__ x, __nv_bfloat16* __restrict__ h,
               __nv_bfloat16* __restrict__ l, size_t n)
{
    size_t i = (size_t)blockIdx.x * 256 + threadIdx.x;
    size_t stride = (size_t)gridDim.x * 256;
    for (; i < n; i += stride) {
        float v = x[i];
        __nv_bfloat16 hi = __float2bfloat16(v);
        h[i] = hi;
        l[i] = __float2bfloat16(v - __bfloat162float(hi));
    }
}

// ---------------------------------------------------------------------------
// Row softmax + dropout mask, emitting split bf16 directly.
// ---------------------------------------------------------------------------
__global__ __launch_bounds__(256)
void softmax_dropout_split(const float* __restrict__ S, const float* __restrict__ u,
                           __nv_bfloat16* __restrict__ Sh, __nv_bfloat16* __restrict__ Sl)
{
    __shared__ float row[NF];
    __shared__ float red[256];

    const int r = blockIdx.x;
    const int tid = threadIdx.x;
    const float* Srow = S + (size_t)r * NF;
    const float* urow = u + (size_t)r * NF;
    const size_t base = (size_t)r * NF;

    float lmax = -INFINITY;
    for (int c = tid; c < NF; c += 256) {
        float v = Srow[c];
        row[c] = v;
        lmax = fmaxf(lmax, v);
    }
    red[tid] = lmax;
    __syncthreads();
    #pragma unroll
    for (int s = 128; s > 0; s >>= 1) {
        if (tid < s) red[tid] = fmaxf(red[tid], red[tid + s]);
        __syncthreads();
    }
    const float m = red[0];
    __syncthreads();

    float lsum = 0.0f;
    for (int c = tid; c < NF; c += 256) {
        float e = __expf(row[c] - m);
        row[c] = e;
        lsum += e;
    }
    red[tid] = lsum;
    __syncthreads();
    #pragma unroll
    for (int s = 128; s > 0; s >>= 1) {
        if (tid < s) red[tid] += red[tid + s];
        __syncthreads();
    }
    const float inv = 1.0f / red[0];

    for (int c = tid; c < NF; c += 256) {
        float keep = (urow[c] >= 0.5f) ? 2.0f : 0.0f;
        float v = row[c] * inv * keep;
        __nv_bfloat16 hb, lb;
        split2(v, hb, lb);
        Sh[base + c] = hb;
        Sl[base + c] = lb;
    }
}

// ---------------------------------------------------------------------------
// Launch
// ---------------------------------------------------------------------------
extern "C" void kernel_launch(void* const* d_in, const int* in_sizes, int n_in,
                              void* d_out, int out_size)
{
    const float* x  = (const float*)d_in[0];
    const float* Wk = (const float*)d_in[1];
    const float* Wq = (const float*)d_in[2];
    const float* Wv = (const float*)d_in[3];
    const float* Wo = (const float*)d_in[4];
    const float* u  = (const float*)d_in[5];
    float* out = (float*)d_out;

    static int attr_set = 0;
    cudaFuncSetAttribute(gemm_mma, cudaFuncAttributeMaxDynamicSharedMemorySize,
                         DYN_SMEM);
    (void)attr_set;

    float* S;
    __nv_bfloat16 *xh, *xl, *Wkh, *Wkl, *Wqh, *Wql, *Wvh, *Wvl, *Woh, *Wol;
    __nv_bfloat16 *Kh, *Kl, *Qh, *Ql, *Vth, *Vtl, *Sh, *Sl, *Yh, *Yl;
    cudaGetSymbolAddress((void**)&S, g_S);
    cudaGetSymbolAddress((void**)&xh, g_xh);   cudaGetSymbolAddress((void**)&xl, g_xl);
    cudaGetSymbolAddress((void**)&Wkh, g_Wkh); cudaGetSymbolAddress((void**)&Wkl, g_Wkl);
    cudaGetSymbolAddress((void**)&Wqh, g_Wqh); cudaGetSymbolAddress((void**)&Wql, g_Wql);
    cudaGetSymbolAddress((void**)&Wvh, g_Wvh); cudaGetSymbolAddress((void**)&Wvl, g_Wvl);
    cudaGetSymbolAddress((void**)&Woh, g_Woh); cudaGetSymbolAddress((void**)&Wol, g_Wol);
    cudaGetSymbolAddress((void**)&Kh, g_Kh);   cudaGetSymbolAddress((void**)&Kl, g_Kl);
    cudaGetSymbolAddress((void**)&Qh, g_Qh);   cudaGetSymbolAddress((void**)&Ql, g_Ql);
    cudaGetSymbolAddress((void**)&Vth, g_Vth); cudaGetSymbolAddress((void**)&Vtl, g_Vtl);
    cudaGetSymbolAddress((void**)&Sh, g_Sh);   cudaGetSymbolAddress((void**)&Sl, g_Sl);
    cudaGetSymbolAddress((void**)&Yh, g_Yh);   cudaGetSymbolAddress((void**)&Yl, g_Yl);

    // 1) split inputs to (hi, lo) bf16
    split_f32<<<4096, 256>>>(x,  xh,  xl,  (size_t)NF * MF);
    split_f32<<<1024, 256>>>(Wk, Wkh, Wkl, (size_t)MF * MF);
    split_f32<<<1024, 256>>>(Wq, Wqh, Wql, (size_t)MF * MF);
    split_f32<<<1024, 256>>>(Wv, Wvh, Wvl, (size_t)MF * MF);
    split_f32<<<1024, 256>>>(Wo, Woh, Wol, (size_t)MF * MF);

    const dim3 blk(256);
    const dim3 gProj(MF / BN, NF / BM);   // (8, 64)
    const dim3 gAttn(NF / BN, NF / BM);   // (64, 64)

    // 2) projections (split bf16 out; V emitted transposed)
    gemm_mma<<<gProj, blk, DYN_SMEM>>>(xh, xl, Wkh, Wkl, nullptr, Kh, Kl,
                                       NF, MF, MF, 1.0f, 1);
    gemm_mma<<<gProj, blk, DYN_SMEM>>>(xh, xl, Wqh, Wql, nullptr, Qh, Ql,
                                       NF, MF, MF, 0.06f, 1);
    gemm_mma<<<gProj, blk, DYN_SMEM>>>(xh, xl, Wvh, Wvl, nullptr, Vth, Vtl,
                                       NF, MF, MF, 1.0f, 2);

    // 3) logits S = Q K^T (fp32 out)
    gemm_mma<<<gAttn, blk, DYN_SMEM>>>(Qh, Ql, Kh, Kl, S, nullptr, nullptr,
                                       NF, NF, MF, 1.0f, 0);

    // 4) softmax + dropout -> split bf16
    softmax_dropout_split<<<NF, blk>>>(S, u, Sh, Sl);

    // 5) Y = W V  (A = S split [N,N], B = V^T split [M,N], K = 8192)
    gemm_mma<<<gProj, blk, DYN_SMEM>>>(Sh, Sl, Vth, Vtl, nullptr, Yh, Yl,
                                       NF, MF, NF, 1.0f, 1);

    // 6) out = Y Wo^T (fp32)
    gemm_mma<<<gProj, blk, DYN_SMEM>>>(Yh, Yl, Woh, Wol, out, nullptr, nullptr,
                                       NF, MF, MF, 1.0f, 0);
}

// round 7
// speedup vs baseline: 2.3967x; 1.0902x over previous
#include <cuda_runtime.h>
#include <cuda_bf16.h>
#include <cstdint>
#include <math.h>

// ---------------------------------------------------------------------------
// SelfAttention via split-bf16 HMMA (mma.sync m16n8k16), warp tile 64x64.
// out = softmax((x Wq^T * 0.06)(x Wk^T)^T)*dropmask @ (x Wv^T) @ Wo^T
// N = 8192, M = 1024. C = Ah*Bh + Ah*Bl + Al*Bh (fp32 acc) ~ fp32-accurate.
// ---------------------------------------------------------------------------

#define NF 8192
#define MF 1024

// ---------------- scratch (__device__ globals; no allocation allowed) ------
__device__ float         g_S [(size_t)NF * NF];                 // 256 MB logits
__device__ __nv_bfloat16 g_Sh[(size_t)NF * NF];                 // 128 MB
__device__ __nv_bfloat16 g_Sl[(size_t)NF * NF];                 // 128 MB
__device__ __nv_bfloat16 g_xh[(size_t)NF * MF], g_xl[(size_t)NF * MF];
__device__ __nv_bfloat16 g_Wkh[(size_t)MF * MF], g_Wkl[(size_t)MF * MF];
__device__ __nv_bfloat16 g_Wqh[(size_t)MF * MF], g_Wql[(size_t)MF * MF];
__device__ __nv_bfloat16 g_Wvh[(size_t)MF * MF], g_Wvl[(size_t)MF * MF];
__device__ __nv_bfloat16 g_Woh[(size_t)MF * MF], g_Wol[(size_t)MF * MF];
__device__ __nv_bfloat16 g_Kh[(size_t)NF * MF], g_Kl[(size_t)NF * MF];
__device__ __nv_bfloat16 g_Qh[(size_t)NF * MF], g_Ql[(size_t)NF * MF];
__device__ __nv_bfloat16 g_Vth[(size_t)MF * NF], g_Vtl[(size_t)MF * NF]; // V^T
__device__ __nv_bfloat16 g_Yh[(size_t)NF * MF], g_Yl[(size_t)NF * MF];

// ---------------- tile config ----------------------------------------------
#define BM 128
#define BN 256
#define BKE 32                    // K elems per chunk (bf16)
#define RS 40                     // smem row stride in elems (padded: 80B)
#define TILE_A_B (BM * RS * 2)    // 10240 B
#define TILE_B_B (BN * RS * 2)    // 20480 B
#define OFF_AH 0
#define OFF_AL (TILE_A_B)
#define OFF_BH (2 * TILE_A_B)
#define OFF_BL (2 * TILE_A_B + TILE_B_B)
#define STAGE_B (2 * TILE_A_B + 2 * TILE_B_B)   // 61440
#define DYN_SMEM (2 * STAGE_B)                   // 122880

// ---------------- PTX helpers ----------------------------------------------
__device__ __forceinline__ uint32_t s2u(const void* p) {
    uint32_t a;
    asm("{ .reg .u64 t; cvta.to.shared.u64 t, %1; cvt.u32.u64 %0, t; }"
        : "=r"(a) : "l"(p));
    return a;
}
__device__ __forceinline__ void cpa16(uint32_t dst, const void* src) {
    asm volatile("cp.async.cg.shared.global [%0], [%1], 16;"
                 :: "r"(dst), "l"(src) : "memory");
}
__device__ __forceinline__ void ldsm4(uint32_t* r, uint32_t addr) {
    asm volatile("ldmatrix.sync.aligned.m8n8.x4.shared.b16 {%0,%1,%2,%3}, [%4];"
                 : "=r"(r[0]), "=r"(r[1]), "=r"(r[2]), "=r"(r[3]) : "r"(addr));
}
__device__ __forceinline__ void mma16816(float* c, const uint32_t* a,
                                         const uint32_t* b) {
    asm volatile(
        "mma.sync.aligned.m16n8k16.row.col.f32.bf16.bf16.f32 "
        "{%0,%1,%2,%3}, {%4,%5,%6,%7}, {%8,%9}, {%0,%1,%2,%3};"
        : "+f"(c[0]), "+f"(c[1]), "+f"(c[2]), "+f"(c[3])
        : "r"(a[0]), "r"(a[1]), "r"(a[2]), "r"(a[3]), "r"(b[0]), "r"(b[1]));
}
__device__ __forceinline__ void split2(float v, __nv_bfloat16& h, __nv_bfloat16& l) {
    h = __float2bfloat16(v);
    l = __float2bfloat16(v - __bfloat162float(h));
}

// ---------------------------------------------------------------------------
// Split-bf16 NT GEMM: C[M,N] = alpha * (Ah+Al)[M,K] * ((Bh+Bl)[N,K])^T
// mode 0: fp32 out (Cf). mode 1: split bf16 out (Ch, Cl).
// mode 2: split bf16 TRANSPOSED out: Ch[col * Mrows + row] (for V^T).
// Requires M mult of 128, N mult of 256, K mult of 32.
// ---------------------------------------------------------------------------
__global__ __launch_bounds__(256, 1)
void gemm_mma(const __nv_bfloat16* __restrict__ Ah, const __nv_bfloat16* __restrict__ Al,
              const __nv_bfloat16* __restrict__ Bh, const __nv_bfloat16* __restrict__ Bl,
              float* __restrict__ Cf,
              __nv_bfloat16* __restrict__ Ch, __nv_bfloat16* __restrict__ Cl,
              int Mrows, int Ncols, int Kdim, float alpha, int mode)
{
    extern __shared__ char dynraw[];
    const uint32_t sbase = s2u(dynraw);

    const int tid  = threadIdx.x;
    const int wid  = tid >> 5;
    const int lane = tid & 31;
    const int bx = blockIdx.x, by = blockIdx.y;

    const int wm = wid & 1;             // warp M origin = wm*64
    const int wn = wid >> 1;            // warp N origin = wn*64 (0..3)
    const int wmBase = wm * 64;
    const int wnBase = wn * 64;

    const size_t rowA0 = (size_t)by * BM;
    const size_t rowB0 = (size_t)bx * BN;

    // loader: one 32-K chunk of all four operand tiles (16B per cp.async)
    auto load_chunk = [&](int kc, int buf) {
        const int k0 = kc * BKE;
        const uint32_t sb = sbase + buf * STAGE_B;
        #pragma unroll
        for (int i = 0; i < 2; i++) {                  // A: 128 rows x 4 chunks
            const int idx = tid + i * 256;
            const int r = idx >> 2, c = idx & 3;
            const uint32_t so = (uint32_t)(r * RS * 2 + c * 16);
            const size_t ga = (rowA0 + r) * (size_t)Kdim + k0 + c * 8;
            cpa16(sb + OFF_AH + so, Ah + ga);
            cpa16(sb + OFF_AL + so, Al + ga);
        }
        #pragma unroll
        for (int i = 0; i < 4; i++) {                  // B: 256 rows x 4 chunks
            const int idx = tid + i * 256;
            const int r = idx >> 2, c = idx & 3;
            const uint32_t so = (uint32_t)(r * RS * 2 + c * 16);
            const size_t gb = (rowB0 + r) * (size_t)Kdim + k0 + c * 8;
            cpa16(sb + OFF_BH + so, Bh + gb);
            cpa16(sb + OFF_BL + so, Bl + gb);
        }
        asm volatile("cp.async.commit_group;" ::: "memory");
    };

    float acc[4][8][4];
    #pragma unroll
    for (int i = 0; i < 4; i++)
        #pragma unroll
        for (int j = 0; j < 8; j++)
            #pragma unroll
            for (int k = 0; k < 4; k++) acc[i][j][k] = 0.0f;

    const int nchunks = Kdim / BKE;
    load_chunk(0, 0);

    // per-lane ldmatrix row/col components
    const int q  = lane >> 3;           // 0..3
    const int r8 = lane & 7;
    const int aRowOff = ((q & 1) ? 8 : 0) + r8;   // A: q&1 -> +8 rows
    const int aKOff   = ((q >> 1) ? 8 : 0);       // A: q>>1 -> +8 k
    const int bRowOff = ((q >> 1) ? 8 : 0) + r8;  // B: q>>1 -> +8 n rows
    const int bKOff   = ((q & 1) ? 8 : 0);        // B: q&1 -> +8 k

    int buf = 0;
    for (int kc = 0; kc < nchunks; kc++) {
        if (kc + 1 < nchunks) {
            load_chunk(kc + 1, 1 - buf);
            asm volatile("cp.async.wait_group 1;" ::: "memory");
        } else {
            asm volatile("cp.async.wait_group 0;" ::: "memory");
        }
        __syncthreads();

        const uint32_t sb = sbase + buf * STAGE_B;
        #pragma unroll
        for (int ks = 0; ks < 2; ks++) {
            uint32_t ah[4][4], alr[4][4];
            #pragma unroll
            for (int am = 0; am < 4; am++) {
                const uint32_t off =
                    (uint32_t)((wmBase + am * 16 + aRowOff) * RS
                               + ks * 16 + aKOff) * 2;
                ldsm4(ah[am],  sb + OFF_AH + off);
                ldsm4(alr[am], sb + OFF_AL + off);
            }
            #pragma unroll
            for (int j = 0; j < 4; j++) {              // n16 groups -> an pairs
                const uint32_t off =
                    (uint32_t)((wnBase + j * 16 + bRowOff) * RS
                               + ks * 16 + bKOff) * 2;
                uint32_t bh2[2][2], bl2[2][2], t[4];
                ldsm4(t, sb + OFF_BH + off);
                bh2[0][0] = t[0]; bh2[0][1] = t[1];
                bh2[1][0] = t[2]; bh2[1][1] = t[3];
                ldsm4(t, sb + OFF_BL + off);
                bl2[0][0] = t[0]; bl2[0][1] = t[1];
                bl2[1][0] = t[2]; bl2[1][1] = t[3];
                #pragma unroll
                for (int am = 0; am < 4; am++)
                    #pragma unroll
                    for (int jj = 0; jj < 2; jj++) {
                        const int an = j * 2 + jj;
                        mma16816(acc[am][an], ah[am],  bh2[jj]);
                        mma16816(acc[am][an], ah[am],  bl2[jj]);
                        mma16816(acc[am][an], alr[am], bh2[jj]);
                    }
            }
        }
        __syncthreads();
        buf ^= 1;
    }

    // ---------------- epilogue --------------------------------------------
    #pragma unroll
    for (int am = 0; am < 4; am++) {
        const int r0 = by * BM + wmBase + am * 16 + (lane >> 2);
        #pragma unroll
        for (int an = 0; an < 8; an++) {
            const int c0 = bx * BN + wnBase + an * 8 + (lane & 3) * 2;
            const float v00 = alpha * acc[am][an][0];
            const float v01 = alpha * acc[am][an][1];
            const float v10 = alpha * acc[am][an][2];
            const float v11 = alpha * acc[am][an][3];
            if (mode == 0) {
                *(float2*)(Cf + (size_t)r0 * Ncols + c0)       = make_float2(v00, v01);
                *(float2*)(Cf + (size_t)(r0 + 8) * Ncols + c0) = make_float2(v10, v11);
            } else if (mode == 1) {
                __nv_bfloat16 h0, l0, h1, l1;
                split2(v00, h0, l0); split2(v01, h1, l1);
                __nv_bfloat162 hp; hp.x = h0; hp.y = h1;
                __nv_bfloat162 lp; lp.x = l0; lp.y = l1;
                *(__nv_bfloat162*)(Ch + (size_t)r0 * Ncols + c0) = hp;
                *(__nv_bfloat162*)(Cl + (size_t)r0 * Ncols + c0) = lp;
                split2(v10, h0, l0); split2(v11, h1, l1);
                hp.x = h0; hp.y = h1; lp.x = l0; lp.y = l1;
                *(__nv_bfloat162*)(Ch + (size_t)(r0 + 8) * Ncols + c0) = hp;
                *(__nv_bfloat162*)(Cl + (size_t)(r0 + 8) * Ncols + c0) = lp;
            } else {                     // transposed split (V^T)
                __nv_bfloat16 h, l;
                split2(v00, h, l);
                Ch[(size_t)c0 * Mrows + r0] = h;       Cl[(size_t)c0 * Mrows + r0] = l;
                split2(v01, h, l);
                Ch[(size_t)(c0 + 1) * Mrows + r0] = h; Cl[(size_t)(c0 + 1) * Mrows + r0] = l;
                split2(v10, h, l);
                Ch[(size_t)c0 * Mrows + r0 + 8] = h;   Cl[(size_t)c0 * Mrows + r0 + 8] = l;
                split2(v11, h, l);
                Ch[(size_t)(c0 + 1) * Mrows + r0 + 8] = h;
                Cl[(size_t)(c0 + 1) * Mrows + r0 + 8] = l;
            }
        }
    }
}

// ---------------------------------------------------------------------------
// fp32 -> (hi, lo) bf16 split (single tensor)
// ---------------------------------------------------------------------------
__global__ __launch_bounds__(256)
void split_f32(const float* __restrict__ x, __nv_bfloat16* __restrict__ h,
               __nv_bfloat16* __restrict__ l, size_t n)
{
    size_t i = (size_t)blockIdx.x * 256 + threadIdx.x;
    size_t stride = (size_t)gridDim.x * 256;
    for (; i < n; i += stride) {
        float v = x[i];
        __nv_bfloat16 hi = __float2bfloat16(v);
        h[i] = hi;
        l[i] = __float2bfloat16(v - __bfloat162float(hi));
    }
}

// fused split of the four MFxMF weight matrices (one launch)
__global__ __launch_bounds__(256)
void split_w4(const float* __restrict__ w0, __nv_bfloat16* __restrict__ h0, __nv_bfloat16* __restrict__ l0,
              const float* __restrict__ w1, __nv_bfloat16* __restrict__ h1, __nv_bfloat16* __restrict__ l1,
              const float* __restrict__ w2, __nv_bfloat16* __restrict__ h2, __nv_bfloat16* __restrict__ l2,
              const float* __restrict__ w3, __nv_bfloat16* __restrict__ h3, __nv_bfloat16* __restrict__ l3)
{
    const size_t n = (size_t)MF * MF;
    size_t i = (size_t)blockIdx.x * 256 + threadIdx.x;
    size_t stride = (size_t)gridDim.x * 256;
    for (; i < n; i += stride) {
        float v; __nv_bfloat16 hb, lb;
        v = w0[i]; split2(v, hb, lb); h0[i] = hb; l0[i] = lb;
        v = w1[i]; split2(v, hb, lb); h1[i] = hb; l1[i] = lb;
        v = w2[i]; split2(v, hb, lb); h2[i] = hb; l2[i] = lb;
        v = w3[i]; split2(v, hb, lb); h3[i] = hb; l3[i] = lb;
    }
}

// ---------------------------------------------------------------------------
// Row softmax + dropout mask, emitting split bf16 directly.
// ---------------------------------------------------------------------------
__global__ __launch_bounds__(256)
void softmax_dropout_split(const float* __restrict__ S, const float* __restrict__ u,
                           __nv_bfloat16* __restrict__ Sh, __nv_bfloat16* __restrict__ Sl)
{
    __shared__ float row[NF];
    __shared__ float red[256];

    const int r = blockIdx.x;
    const int tid = threadIdx.x;
    const float* Srow = S + (size_t)r * NF;
    const float* urow = u + (size_t)r * NF;
    const size_t base = (size_t)r * NF;

    float lmax = -INFINITY;
    for (int c = tid; c < NF; c += 256) {
        float v = Srow[c];
        row[c] = v;
        lmax = fmaxf(lmax, v);
    }
    red[tid] = lmax;
    __syncthreads();
    #pragma unroll
    for (int s = 128; s > 0; s >>= 1) {
        if (tid < s) red[tid] = fmaxf(red[tid], red[tid + s]);
        __syncthreads();
    }
    const float m = red[0];
    __syncthreads();

    float lsum = 0.0f;
    for (int c = tid; c < NF; c += 256) {
        float e = __expf(row[c] - m);
        row[c] = e;
        lsum += e;
    }
    red[tid] = lsum;
    __syncthreads();
    #pragma unroll
    for (int s = 128; s > 0; s >>= 1) {
        if (tid < s) red[tid] += red[tid + s];
        __syncthreads();
    }
    const float inv = 1.0f / red[0];

    for (int c = tid; c < NF; c += 256) {
        float keep = (urow[c] >= 0.5f) ? 2.0f : 0.0f;
        float v = row[c] * inv * keep;
        __nv_bfloat16 hb, lb;
        split2(v, hb, lb);
        Sh[base + c] = hb;
        Sl[base + c] = lb;
    }
}

// ---------------------------------------------------------------------------
// Launch
// ---------------------------------------------------------------------------
extern "C" void kernel_launch(void* const* d_in, const int* in_sizes, int n_in,
                              void* d_out, int out_size)
{
    const float* x  = (const float*)d_in[0];
    const float* Wk = (const float*)d_in[1];
    const float* Wq = (const float*)d_in[2];
    const float* Wv = (const float*)d_in[3];
    const float* Wo = (const float*)d_in[4];
    const float* u  = (const float*)d_in[5];
    float* out = (float*)d_out;

    cudaFuncSetAttribute(gemm_mma, cudaFuncAttributeMaxDynamicSharedMemorySize,
                         DYN_SMEM);

    float* S;
    __nv_bfloat16 *xh, *xl, *Wkh, *Wkl, *Wqh, *Wql, *Wvh, *Wvl, *Woh, *Wol;
    __nv_bfloat16 *Kh, *Kl, *Qh, *Ql, *Vth, *Vtl, *Sh, *Sl, *Yh, *Yl;
    cudaGetSymbolAddress((void**)&S, g_S);
    cudaGetSymbolAddress((void**)&xh, g_xh);   cudaGetSymbolAddress((void**)&xl, g_xl);
    cudaGetSymbolAddress((void**)&Wkh, g_Wkh); cudaGetSymbolAddress((void**)&Wkl, g_Wkl);
    cudaGetSymbolAddress((void**)&Wqh, g_Wqh); cudaGetSymbolAddress((void**)&Wql, g_Wql);
    cudaGetSymbolAddress((void**)&Wvh, g_Wvh); cudaGetSymbolAddress((void**)&Wvl, g_Wvl);
    cudaGetSymbolAddress((void**)&Woh, g_Woh); cudaGetSymbolAddress((void**)&Wol, g_Wol);
    cudaGetSymbolAddress((void**)&Kh, g_Kh);   cudaGetSymbolAddress((void**)&Kl, g_Kl);
    cudaGetSymbolAddress((void**)&Qh, g_Qh);   cudaGetSymbolAddress((void**)&Ql, g_Ql);
    cudaGetSymbolAddress((void**)&Vth, g_Vth); cudaGetSymbolAddress((void**)&Vtl, g_Vtl);
    cudaGetSymbolAddress((void**)&Sh, g_Sh);   cudaGetSymbolAddress((void**)&Sl, g_Sl);
    cudaGetSymbolAddress((void**)&Yh, g_Yh);   cudaGetSymbolAddress((void**)&Yl, g_Yl);

    // 1) split inputs to (hi, lo) bf16 — 2 launches total
    split_f32<<<4096, 256>>>(x, xh, xl, (size_t)NF * MF);            // launch 0
    split_w4<<<1024, 256>>>(Wk, Wkh, Wkl, Wq, Wqh, Wql,
                            Wv, Wvh, Wvl, Wo, Woh, Wol);             // launch 1

    const dim3 blk(256);
    const dim3 gProj(MF / BN, NF / BM);   // (4, 64)
    const dim3 gAttn(NF / BN, NF / BM);   // (32, 64)

    // 2) projections (split bf16 out; V emitted transposed)
    gemm_mma<<<gProj, blk, DYN_SMEM>>>(xh, xl, Wkh, Wkl, nullptr, Kh, Kl,
                                       NF, MF, MF, 1.0f, 1);         // launch 2
    gemm_mma<<<gProj, blk, DYN_SMEM>>>(xh, xl, Wqh, Wql, nullptr, Qh, Ql,
                                       NF, MF, MF, 0.06f, 1);        // launch 3
    gemm_mma<<<gProj, blk, DYN_SMEM>>>(xh, xl, Wvh, Wvl, nullptr, Vth, Vtl,
                                       NF, MF, MF, 1.0f, 2);         // launch 4

    // 3) logits S = Q K^T (fp32 out) — launch 5: ncu -s 5 -c 1 captures this
    gemm_mma<<<gAttn, blk, DYN_SMEM>>>(Qh, Ql, Kh, Kl, S, nullptr, nullptr,
                                       NF, NF, MF, 1.0f, 0);

    // 4) softmax + dropout -> split bf16
    softmax_dropout_split<<<NF, blk>>>(S, u, Sh, Sl);

    // 5) Y = W V  (A = S split [N,N], B = V^T split [M,N], K = 8192)
    gemm_mma<<<gProj, blk, DYN_SMEM>>>(Sh, Sl, Vth, Vtl, nullptr, Yh, Yl,
                                       NF, MF, NF, 1.0f, 1);

    // 6) out = Y Wo^T (fp32)
    gemm_mma<<<gProj, blk, DYN_SMEM>>>(Yh, Yl, Woh, Wol, out, nullptr, nullptr,
                                       NF, MF, MF, 1.0f, 0);
}

// round 8
// speedup vs baseline: 3.3355x; 1.3917x over previous
#include <cuda_runtime.h>
#include <cuda_fp16.h>
#include <cstdint>
#include <math.h>

// ---------------------------------------------------------------------------
// SelfAttention via split-fp16 HMMA (mma.sync m16n8k16.f32.f16.f16.f32).
// out = softmax((x Wq^T * 0.06)(x Wk^T)^T)*dropmask @ (x Wv^T) @ Wo^T
// N = 8192, M = 1024.
// Precision scheme: B operands split (Bh + Bl fp16), A operands fp16 hi only.
//   C = Ah*Bh + Ah*Bl   (2 MMA passes; dropped Al*B term ~2^-12 relative)
// ---------------------------------------------------------------------------

#define NF 8192
#define MF 1024

// ---------------- scratch (__device__ globals; no allocation allowed) ------
__device__ float  g_S [(size_t)NF * NF];                 // 256 MB logits
__device__ __half g_Sh[(size_t)NF * NF];                 // 128 MB (A side: hi only)
__device__ __half g_xh[(size_t)NF * MF];                 // x: A side, hi only
__device__ __half g_Wkh[(size_t)MF * MF], g_Wkl[(size_t)MF * MF];
__device__ __half g_Wqh[(size_t)MF * MF], g_Wql[(size_t)MF * MF];
__device__ __half g_Wvh[(size_t)MF * MF], g_Wvl[(size_t)MF * MF];
__device__ __half g_Woh[(size_t)MF * MF], g_Wol[(size_t)MF * MF];
__device__ __half g_Kh[(size_t)NF * MF], g_Kl[(size_t)NF * MF];   // B in QK^T
__device__ __half g_Qh[(size_t)NF * MF];                          // A: hi only
__device__ __half g_Vth[(size_t)MF * NF], g_Vtl[(size_t)MF * NF]; // V^T: B side
__device__ __half g_Yh[(size_t)NF * MF];                          // A: hi only

// ---------------- tile config ----------------------------------------------
#define BM 128
#define BN 256
#define BKE 32                    // K elems per chunk (fp16)
#define RS 40                     // smem row stride in elems (80 B, conflict-free)
#define TILE_A_B (BM * RS * 2)    // 10240 B
#define TILE_B_B (BN * RS * 2)    // 20480 B
#define OFF_A  0
#define OFF_BH (TILE_A_B)
#define OFF_BL (TILE_A_B + TILE_B_B)
#define STAGE_B (TILE_A_B + 2 * TILE_B_B)        // 51200
#define NSTAGE 3
#define DYN_SMEM (NSTAGE * STAGE_B)              // 153600

// ---------------- PTX helpers ----------------------------------------------
__device__ __forceinline__ uint32_t s2u(const void* p) {
    uint32_t a;
    asm("{ .reg .u64 t; cvta.to.shared.u64 t, %1; cvt.u32.u64 %0, t; }"
        : "=r"(a) : "l"(p));
    return a;
}
__device__ __forceinline__ void cpa16(uint32_t dst, const void* src) {
    asm volatile("cp.async.cg.shared.global [%0], [%1], 16;"
                 :: "r"(dst), "l"(src) : "memory");
}
__device__ __forceinline__ void ldsm4(uint32_t* r, uint32_t addr) {
    asm volatile("ldmatrix.sync.aligned.m8n8.x4.shared.b16 {%0,%1,%2,%3}, [%4];"
                 : "=r"(r[0]), "=r"(r[1]), "=r"(r[2]), "=r"(r[3]) : "r"(addr));
}
__device__ __forceinline__ void mma16816(float* c, const uint32_t* a,
                                         const uint32_t* b) {
    asm volatile(
        "mma.sync.aligned.m16n8k16.row.col.f32.f16.f16.f32 "
        "{%0,%1,%2,%3}, {%4,%5,%6,%7}, {%8,%9}, {%0,%1,%2,%3};"
        : "+f"(c[0]), "+f"(c[1]), "+f"(c[2]), "+f"(c[3])
        : "r"(a[0]), "r"(a[1]), "r"(a[2]), "r"(a[3]), "r"(b[0]), "r"(b[1]));
}
__device__ __forceinline__ void split2h(float v, __half& h, __half& l) {
    h = __float2half_rn(v);
    l = __float2half_rn(v - __half2float(h));
}

// ---------------------------------------------------------------------------
// NT GEMM: C[M,N] = alpha * Ah[M,K] * ((Bh+Bl)[N,K])^T   (2 MMA passes)
// mode 0: fp32 out (Cf).
// mode 1: split fp16 out (Ch + Cl), row-major.
// mode 2: split fp16 TRANSPOSED out: Ch[col*Mrows + row] (for V^T).
// mode 3: fp16 hi-only out (Ch), row-major.
// Requires M mult of 128, N mult of 256, K mult of 32.
// ---------------------------------------------------------------------------
__global__ __launch_bounds__(256, 1)
void gemm_mma(const __half* __restrict__ Ah,
              const __half* __restrict__ Bh, const __half* __restrict__ Bl,
              float* __restrict__ Cf,
              __half* __restrict__ Ch, __half* __restrict__ Cl,
              int Mrows, int Ncols, int Kdim, float alpha, int mode)
{
    extern __shared__ char dynraw[];
    const uint32_t sbase = s2u(dynraw);

    const int tid  = threadIdx.x;
    const int wid  = tid >> 5;
    const int lane = tid & 31;
    const int bx = blockIdx.x, by = blockIdx.y;

    const int wmBase = (wid & 1) * 64;      // warp M origin
    const int wnBase = (wid >> 1) * 64;     // warp N origin (0..3 -> 0..192)

    const size_t rowA0 = (size_t)by * BM;
    const size_t rowB0 = (size_t)bx * BN;

    // loader: one 32-K chunk (A hi 10KB + B hi/lo 40KB), one commit group
    auto load_chunk = [&](int kc, int stg) {
        const int k0 = kc * BKE;
        const uint32_t sb = sbase + stg * STAGE_B;
        #pragma unroll
        for (int i = 0; i < 2; i++) {                  // A: 128 rows x 4 x 16B
            const int idx = tid + i * 256;
            const int r = idx >> 2, c = idx & 3;
            const uint32_t so = (uint32_t)(r * RS * 2 + c * 16);
            cpa16(sb + OFF_A + so, Ah + (rowA0 + r) * (size_t)Kdim + k0 + c * 8);
        }
        #pragma unroll
        for (int i = 0; i < 4; i++) {                  // B: 256 rows x 4 x 16B
            const int idx = tid + i * 256;
            const int r = idx >> 2, c = idx & 3;
            const uint32_t so = (uint32_t)(r * RS * 2 + c * 16);
            const size_t gb = (rowB0 + r) * (size_t)Kdim + k0 + c * 8;
            cpa16(sb + OFF_BH + so, Bh + gb);
            cpa16(sb + OFF_BL + so, Bl + gb);
        }
        asm volatile("cp.async.commit_group;" ::: "memory");
    };

    float acc[4][8][4];
    #pragma unroll
    for (int i = 0; i < 4; i++)
        #pragma unroll
        for (int j = 0; j < 8; j++)
            #pragma unroll
            for (int k = 0; k < 4; k++) acc[i][j][k] = 0.0f;

    const int nchunks = Kdim / BKE;

    // per-lane ldmatrix addressing components
    const int q  = lane >> 3;
    const int r8 = lane & 7;
    const int aRowOff = ((q & 1) ? 8 : 0) + r8;
    const int aKOff   = ((q >> 1) ? 8 : 0);
    const int bRowOff = ((q >> 1) ? 8 : 0) + r8;
    const int bKOff   = ((q & 1) ? 8 : 0);

    // 3-stage pipeline prologue
    load_chunk(0, 0);
    if (nchunks > 1) load_chunk(1, 1);

    for (int kc = 0; kc < nchunks; kc++) {
        if (kc + 1 < nchunks) {
            asm volatile("cp.async.wait_group 1;" ::: "memory");
        } else {
            asm volatile("cp.async.wait_group 0;" ::: "memory");
        }
        __syncthreads();   // chunk kc resident; all warps done with stage (kc-1)%3

        if (kc + 2 < nchunks) load_chunk(kc + 2, (kc + 2) % NSTAGE);

        const uint32_t sb = sbase + (kc % NSTAGE) * STAGE_B;
        #pragma unroll
        for (int ks = 0; ks < 2; ks++) {
            uint32_t ah[4][4];
            #pragma unroll
            for (int am = 0; am < 4; am++) {
                const uint32_t off =
                    (uint32_t)((wmBase + am * 16 + aRowOff) * RS
                               + ks * 16 + aKOff) * 2;
                ldsm4(ah[am], sb + OFF_A + off);
            }
            #pragma unroll
            for (int j = 0; j < 4; j++) {
                const uint32_t off =
                    (uint32_t)((wnBase + j * 16 + bRowOff) * RS
                               + ks * 16 + bKOff) * 2;
                uint32_t bh[4], bl[4];
                ldsm4(bh, sb + OFF_BH + off);
                ldsm4(bl, sb + OFF_BL + off);
                #pragma unroll
                for (int am = 0; am < 4; am++) {
                    mma16816(acc[am][j * 2],     ah[am], bh);
                    mma16816(acc[am][j * 2 + 1], ah[am], bh + 2);
                    mma16816(acc[am][j * 2],     ah[am], bl);
                    mma16816(acc[am][j * 2 + 1], ah[am], bl + 2);
                }
            }
        }
    }

    // ---------------- epilogue --------------------------------------------
    #pragma unroll
    for (int am = 0; am < 4; am++) {
        const int r0 = by * BM + wmBase + am * 16 + (lane >> 2);
        #pragma unroll
        for (int an = 0; an < 8; an++) {
            const int c0 = bx * BN + wnBase + an * 8 + (lane & 3) * 2;
            const float v00 = alpha * acc[am][an][0];
            const float v01 = alpha * acc[am][an][1];
            const float v10 = alpha * acc[am][an][2];
            const float v11 = alpha * acc[am][an][3];
            if (mode == 0) {
                *(float2*)(Cf + (size_t)r0 * Ncols + c0)       = make_float2(v00, v01);
                *(float2*)(Cf + (size_t)(r0 + 8) * Ncols + c0) = make_float2(v10, v11);
            } else if (mode == 1) {
                __half h0, l0, h1, l1;
                split2h(v00, h0, l0); split2h(v01, h1, l1);
                *(__half2*)(Ch + (size_t)r0 * Ncols + c0) = __halves2half2(h0, h1);
                *(__half2*)(Cl + (size_t)r0 * Ncols + c0) = __halves2half2(l0, l1);
                split2h(v10, h0, l0); split2h(v11, h1, l1);
                *(__half2*)(Ch + (size_t)(r0 + 8) * Ncols + c0) = __halves2half2(h0, h1);
                *(__half2*)(Cl + (size_t)(r0 + 8) * Ncols + c0) = __halves2half2(l0, l1);
            } else if (mode == 2) {          // transposed split (V^T)
                __half h, l;
                split2h(v00, h, l);
                Ch[(size_t)c0 * Mrows + r0] = h;       Cl[(size_t)c0 * Mrows + r0] = l;
                split2h(v01, h, l);
                Ch[(size_t)(c0 + 1) * Mrows + r0] = h; Cl[(size_t)(c0 + 1) * Mrows + r0] = l;
                split2h(v10, h, l);
                Ch[(size_t)c0 * Mrows + r0 + 8] = h;   Cl[(size_t)c0 * Mrows + r0 + 8] = l;
                split2h(v11, h, l);
                Ch[(size_t)(c0 + 1) * Mrows + r0 + 8] = h;
                Cl[(size_t)(c0 + 1) * Mrows + r0 + 8] = l;
            } else {                         // mode 3: fp16 hi only
                *(__half2*)(Ch + (size_t)r0 * Ncols + c0) =
                    __halves2half2(__float2half_rn(v00), __float2half_rn(v01));
                *(__half2*)(Ch + (size_t)(r0 + 8) * Ncols + c0) =
                    __halves2half2(__float2half_rn(v10), __float2half_rn(v11));
            }
        }
    }
}

// ---------------------------------------------------------------------------
// fp32 -> fp16 (hi only), for A-side tensors
// ---------------------------------------------------------------------------
__global__ __launch_bounds__(256)
void cast_f32_f16(const float* __restrict__ x, __half* __restrict__ h, size_t n)
{
    size_t i = (size_t)blockIdx.x * 256 + threadIdx.x;
    size_t stride = (size_t)gridDim.x * 256;
    for (; i < n; i += stride) h[i] = __float2half_rn(x[i]);
}

// fused (hi,lo) split of the four MFxMF weight matrices (one launch)
__global__ __launch_bounds__(256)
void split_w4(const float* __restrict__ w0, __half* __restrict__ h0, __half* __restrict__ l0,
              const float* __restrict__ w1, __half* __restrict__ h1, __half* __restrict__ l1,
              const float* __restrict__ w2, __half* __restrict__ h2, __half* __restrict__ l2,
              const float* __restrict__ w3, __half* __restrict__ h3, __half* __restrict__ l3)
{
    const size_t n = (size_t)MF * MF;
    size_t i = (size_t)blockIdx.x * 256 + threadIdx.x;
    size_t stride = (size_t)gridDim.x * 256;
    for (; i < n; i += stride) {
        float v; __half hb, lb;
        v = w0[i]; split2h(v, hb, lb); h0[i] = hb; l0[i] = lb;
        v = w1[i]; split2h(v, hb, lb); h1[i] = hb; l1[i] = lb;
        v = w2[i]; split2h(v, hb, lb); h2[i] = hb; l2[i] = lb;
        v = w3[i]; split2h(v, hb, lb); h3[i] = hb; l3[i] = lb;
    }
}

// ---------------------------------------------------------------------------
// Row softmax + dropout mask, emitting fp16 hi-only (A side of S@V).
// ---------------------------------------------------------------------------
__global__ __launch_bounds__(256)
void softmax_dropout_h(const float* __restrict__ S, const float* __restrict__ u,
                       __half* __restrict__ Sh)
{
    __shared__ float row[NF];
    __shared__ float red[256];

    const int r = blockIdx.x;
    const int tid = threadIdx.x;
    const float* Srow = S + (size_t)r * NF;
    const float* urow = u + (size_t)r * NF;
    const size_t base = (size_t)r * NF;

    float lmax = -INFINITY;
    for (int c = tid; c < NF; c += 256) {
        float v = Srow[c];
        row[c] = v;
        lmax = fmaxf(lmax, v);
    }
    red[tid] = lmax;
    __syncthreads();
    #pragma unroll
    for (int s = 128; s > 0; s >>= 1) {
        if (tid < s) red[tid] = fmaxf(red[tid], red[tid + s]);
        __syncthreads();
    }
    const float m = red[0];
    __syncthreads();

    float lsum = 0.0f;
    for (int c = tid; c < NF; c += 256) {
        float e = __expf(row[c] - m);
        row[c] = e;
        lsum += e;
    }
    red[tid] = lsum;
    __syncthreads();
    #pragma unroll
    for (int s = 128; s > 0; s >>= 1) {
        if (tid < s) red[tid] += red[tid + s];
        __syncthreads();
    }
    const float inv = 1.0f / red[0];

    for (int c = tid; c < NF; c += 256) {
        float keep = (urow[c] >= 0.5f) ? 2.0f : 0.0f;
        Sh[base + c] = __float2half_rn(row[c] * inv * keep);
    }
}

// ---------------------------------------------------------------------------
// Launch
// ---------------------------------------------------------------------------
extern "C" void kernel_launch(void* const* d_in, const int* in_sizes, int n_in,
                              void* d_out, int out_size)
{
    const float* x  = (const float*)d_in[0];
    const float* Wk = (const float*)d_in[1];
    const float* Wq = (const float*)d_in[2];
    const float* Wv = (const float*)d_in[3];
    const float* Wo = (const float*)d_in[4];
    const float* u  = (const float*)d_in[5];
    float* out = (float*)d_out;

    cudaFuncSetAttribute(gemm_mma, cudaFuncAttributeMaxDynamicSharedMemorySize,
                         DYN_SMEM);

    float* S;
    __half *xh, *Wkh, *Wkl, *Wqh, *Wql, *Wvh, *Wvl, *Woh, *Wol;
    __half *Kh, *Kl, *Qh, *Vth, *Vtl, *Sh, *Yh;
    cudaGetSymbolAddress((void**)&S, g_S);
    cudaGetSymbolAddress((void**)&xh, g_xh);
    cudaGetSymbolAddress((void**)&Wkh, g_Wkh); cudaGetSymbolAddress((void**)&Wkl, g_Wkl);
    cudaGetSymbolAddress((void**)&Wqh, g_Wqh); cudaGetSymbolAddress((void**)&Wql, g_Wql);
    cudaGetSymbolAddress((void**)&Wvh, g_Wvh); cudaGetSymbolAddress((void**)&Wvl, g_Wvl);
    cudaGetSymbolAddress((void**)&Woh, g_Woh); cudaGetSymbolAddress((void**)&Wol, g_Wol);
    cudaGetSymbolAddress((void**)&Kh, g_Kh);   cudaGetSymbolAddress((void**)&Kl, g_Kl);
    cudaGetSymbolAddress((void**)&Qh, g_Qh);
    cudaGetSymbolAddress((void**)&Vth, g_Vth); cudaGetSymbolAddress((void**)&Vtl, g_Vtl);
    cudaGetSymbolAddress((void**)&Sh, g_Sh);
    cudaGetSymbolAddress((void**)&Yh, g_Yh);

    // 1) conversions
    cast_f32_f16<<<4096, 256>>>(x, xh, (size_t)NF * MF);             // launch 0
    split_w4<<<1024, 256>>>(Wk, Wkh, Wkl, Wq, Wqh, Wql,
                            Wv, Wvh, Wvl, Wo, Woh, Wol);             // launch 1

    const dim3 blk(256);
    const dim3 gProj(MF / BN, NF / BM);   // (4, 64)
    const dim3 gAttn(NF / BN, NF / BM);   // (32, 64)

    // 2) projections
    gemm_mma<<<gProj, blk, DYN_SMEM>>>(xh, Wkh, Wkl, nullptr, Kh, Kl,
                                       NF, MF, MF, 1.0f, 1);         // launch 2
    gemm_mma<<<gProj, blk, DYN_SMEM>>>(xh, Wqh, Wql, nullptr, Qh, nullptr,
                                       NF, MF, MF, 0.06f, 3);        // launch 3
    gemm_mma<<<gProj, blk, DYN_SMEM>>>(xh, Wvh, Wvl, nullptr, Vth, Vtl,
                                       NF, MF, MF, 1.0f, 2);         // launch 4

    // 3) logits S = Q K^T (fp32) — launch 5 for ncu
    gemm_mma<<<gAttn, blk, DYN_SMEM>>>(Qh, Kh, Kl, S, nullptr, nullptr,
                                       NF, NF, MF, 1.0f, 0);

    // 4) softmax + dropout -> fp16
    softmax_dropout_h<<<NF, blk>>>(S, u, Sh);

    // 5) Y = W V  (A = Sh [N,N], B = V^T split [M,N], K = 8192)
    gemm_mma<<<gProj, blk, DYN_SMEM>>>(Sh, Vth, Vtl, nullptr, Yh, nullptr,
                                       NF, MF, NF, 1.0f, 3);

    // 6) out = Y Wo^T (fp32)
    gemm_mma<<<gProj, blk, DYN_SMEM>>>(Yh, Woh, Wol, out, nullptr, nullptr,
                                       NF, MF, MF, 1.0f, 0);
}

// round 10
// speedup vs baseline: 3.6871x; 1.1054x over previous
#include <cuda_runtime.h>
#include <cuda_fp16.h>
#include <cstdint>
#include <math.h>

// ---------------------------------------------------------------------------
// SelfAttention via split-fp16 HMMA (mma.sync m16n8k16.f32.f16.f16.f32).
// out = softmax((x Wq^T * 0.06)(x Wk^T)^T)*dropmask @ (x Wv^T) @ Wo^T
// N = 8192, M = 1024.
// Precision: B split (Bh+Bl fp16), A fp16 hi-only. C = Ah*Bh + Ah*Bl.
// R10: R9 design (128-thr CTA, 2 CTAs/SM, RAW-spread MMA order) with the
//      softmax launch-config bug fixed (softmax needs 256 threads).
// ---------------------------------------------------------------------------

#define NF 8192
#define MF 1024

// ---------------- scratch (__device__ globals) ------------------------------
__device__ float  g_S [(size_t)NF * NF];                 // 256 MB logits
__device__ __half g_Sh[(size_t)NF * NF];                 // 128 MB (A side)
__device__ __half g_xh[(size_t)NF * MF];
__device__ __half g_Wkh[(size_t)MF * MF], g_Wkl[(size_t)MF * MF];
__device__ __half g_Wqh[(size_t)MF * MF], g_Wql[(size_t)MF * MF];
__device__ __half g_Wvh[(size_t)MF * MF], g_Wvl[(size_t)MF * MF];
__device__ __half g_Woh[(size_t)MF * MF], g_Wol[(size_t)MF * MF];
__device__ __half g_Kh[(size_t)NF * MF], g_Kl[(size_t)NF * MF];
__device__ __half g_Qh[(size_t)NF * MF];
__device__ __half g_Vth[(size_t)MF * NF], g_Vtl[(size_t)MF * NF]; // V^T
__device__ __half g_Yh[(size_t)NF * MF];

// ---------------- tile config ----------------------------------------------
#define BM 128
#define BN 128
#define BKE 32                    // K elems per chunk (fp16)
#define RS 40                     // smem row stride in elems (80 B)
#define TILE_T_B (BM * RS * 2)    // 10240 B per tile (A, Bh, Bl all 128 rows)
#define OFF_A  0
#define OFF_BH (TILE_T_B)
#define OFF_BL (2 * TILE_T_B)
#define STAGE_B (3 * TILE_T_B)    // 30720
#define NSTAGE 3
#define DYN_SMEM (NSTAGE * STAGE_B)   // 92160 per CTA (2 CTAs -> 184 KB/SM)

// ---------------- PTX helpers ----------------------------------------------
__device__ __forceinline__ uint32_t s2u(const void* p) {
    uint32_t a;
    asm("{ .reg .u64 t; cvta.to.shared.u64 t, %1; cvt.u32.u64 %0, t; }"
        : "=r"(a) : "l"(p));
    return a;
}
__device__ __forceinline__ void cpa16(uint32_t dst, const void* src) {
    asm volatile("cp.async.cg.shared.global [%0], [%1], 16;"
                 :: "r"(dst), "l"(src) : "memory");
}
__device__ __forceinline__ void ldsm4(uint32_t* r, uint32_t addr) {
    asm volatile("ldmatrix.sync.aligned.m8n8.x4.shared.b16 {%0,%1,%2,%3}, [%4];"
                 : "=r"(r[0]), "=r"(r[1]), "=r"(r[2]), "=r"(r[3]) : "r"(addr));
}
__device__ __forceinline__ void mma16816(float* c, const uint32_t* a,
                                         const uint32_t* b) {
    asm volatile(
        "mma.sync.aligned.m16n8k16.row.col.f32.f16.f16.f32 "
        "{%0,%1,%2,%3}, {%4,%5,%6,%7}, {%8,%9}, {%0,%1,%2,%3};"
        : "+f"(c[0]), "+f"(c[1]), "+f"(c[2]), "+f"(c[3])
        : "r"(a[0]), "r"(a[1]), "r"(a[2]), "r"(a[3]), "r"(b[0]), "r"(b[1]));
}
__device__ __forceinline__ void split2h(float v, __half& h, __half& l) {
    h = __float2half_rn(v);
    l = __float2half_rn(v - __half2float(h));
}

// ---------------------------------------------------------------------------
// NT GEMM: C[M,N] = alpha * Ah[M,K] * ((Bh+Bl)[N,K])^T   (2 MMA passes)
// mode 0: fp32 out. mode 1: split fp16 out. mode 2: split fp16 transposed.
// mode 3: fp16 hi-only out. Requires M,N mult of 128, K mult of 32.
// ---------------------------------------------------------------------------
__global__ __launch_bounds__(128, 2)
void gemm_mma(const __half* __restrict__ Ah,
              const __half* __restrict__ Bh, const __half* __restrict__ Bl,
              float* __restrict__ Cf,
              __half* __restrict__ Ch, __half* __restrict__ Cl,
              int Mrows, int Ncols, int Kdim, float alpha, int mode)
{
    extern __shared__ char dynraw[];
    const uint32_t sbase = s2u(dynraw);

    const int tid  = threadIdx.x;
    const int wid  = tid >> 5;
    const int lane = tid & 31;
    const int bx = blockIdx.x, by = blockIdx.y;

    const int wmBase = (wid & 1) * 64;      // warp M origin
    const int wnBase = (wid >> 1) * 64;     // warp N origin

    const size_t rowA0 = (size_t)by * BM;
    const size_t rowB0 = (size_t)bx * BN;

    // loader: one 32-K chunk (A + Bh + Bl, each 128 rows x 4 x 16B)
    auto load_chunk = [&](int kc, int stg) {
        const int k0 = kc * BKE;
        const uint32_t sb = sbase + stg * STAGE_B;
        #pragma unroll
        for (int i = 0; i < 4; i++) {
            const int idx = tid + i * 128;             // 0..511
            const int r = idx >> 2, c = idx & 3;
            const uint32_t so = (uint32_t)(r * RS * 2 + c * 16);
            cpa16(sb + OFF_A + so, Ah + (rowA0 + r) * (size_t)Kdim + k0 + c * 8);
            const size_t gb = (rowB0 + r) * (size_t)Kdim + k0 + c * 8;
            cpa16(sb + OFF_BH + so, Bh + gb);
            cpa16(sb + OFF_BL + so, Bl + gb);
        }
        asm volatile("cp.async.commit_group;" ::: "memory");
    };

    float acc[4][8][4];
    #pragma unroll
    for (int i = 0; i < 4; i++)
        #pragma unroll
        for (int j = 0; j < 8; j++)
            #pragma unroll
            for (int k = 0; k < 4; k++) acc[i][j][k] = 0.0f;

    const int nchunks = Kdim / BKE;

    const int q  = lane >> 3;
    const int r8 = lane & 7;
    const int aRowOff = ((q & 1) ? 8 : 0) + r8;
    const int aKOff   = ((q >> 1) ? 8 : 0);
    const int bRowOff = ((q >> 1) ? 8 : 0) + r8;
    const int bKOff   = ((q & 1) ? 8 : 0);

    load_chunk(0, 0);
    if (nchunks > 1) load_chunk(1, 1);

    for (int kc = 0; kc < nchunks; kc++) {
        if (kc + 1 < nchunks) {
            asm volatile("cp.async.wait_group 1;" ::: "memory");
        } else {
            asm volatile("cp.async.wait_group 0;" ::: "memory");
        }
        __syncthreads();

        if (kc + 2 < nchunks) load_chunk(kc + 2, (kc + 2) % NSTAGE);

        const uint32_t sb = sbase + (kc % NSTAGE) * STAGE_B;
        #pragma unroll
        for (int ks = 0; ks < 2; ks++) {
            uint32_t ah[4][4], bh[4][4], bl[4][4];
            #pragma unroll
            for (int am = 0; am < 4; am++) {
                const uint32_t off =
                    (uint32_t)((wmBase + am * 16 + aRowOff) * RS
                               + ks * 16 + aKOff) * 2;
                ldsm4(ah[am], sb + OFF_A + off);
            }
            #pragma unroll
            for (int j = 0; j < 4; j++) {
                const uint32_t off =
                    (uint32_t)((wnBase + j * 16 + bRowOff) * RS
                               + ks * 16 + bKOff) * 2;
                ldsm4(bh[j], sb + OFF_BH + off);
                ldsm4(bl[j], sb + OFF_BL + off);
            }
            // hi pass (32 MMAs), then lo pass: acc reuse distance = 8 MMAs
            #pragma unroll
            for (int j = 0; j < 4; j++)
                #pragma unroll
                for (int am = 0; am < 4; am++) {
                    mma16816(acc[am][j * 2],     ah[am], bh[j]);
                    mma16816(acc[am][j * 2 + 1], ah[am], bh[j] + 2);
                }
            #pragma unroll
            for (int j = 0; j < 4; j++)
                #pragma unroll
                for (int am = 0; am < 4; am++) {
                    mma16816(acc[am][j * 2],     ah[am], bl[j]);
                    mma16816(acc[am][j * 2 + 1], ah[am], bl[j] + 2);
                }
        }
    }

    // ---------------- epilogue --------------------------------------------
    #pragma unroll
    for (int am = 0; am < 4; am++) {
        const int r0 = by * BM + wmBase + am * 16 + (lane >> 2);
        #pragma unroll
        for (int an = 0; an < 8; an++) {
            const int c0 = bx * BN + wnBase + an * 8 + (lane & 3) * 2;
            const float v00 = alpha * acc[am][an][0];
            const float v01 = alpha * acc[am][an][1];
            const float v10 = alpha * acc[am][an][2];
            const float v11 = alpha * acc[am][an][3];
            if (mode == 0) {
                *(float2*)(Cf + (size_t)r0 * Ncols + c0)       = make_float2(v00, v01);
                *(float2*)(Cf + (size_t)(r0 + 8) * Ncols + c0) = make_float2(v10, v11);
            } else if (mode == 1) {
                __half h0, l0, h1, l1;
                split2h(v00, h0, l0); split2h(v01, h1, l1);
                *(__half2*)(Ch + (size_t)r0 * Ncols + c0) = __halves2half2(h0, h1);
                *(__half2*)(Cl + (size_t)r0 * Ncols + c0) = __halves2half2(l0, l1);
                split2h(v10, h0, l0); split2h(v11, h1, l1);
                *(__half2*)(Ch + (size_t)(r0 + 8) * Ncols + c0) = __halves2half2(h0, h1);
                *(__half2*)(Cl + (size_t)(r0 + 8) * Ncols + c0) = __halves2half2(l0, l1);
            } else if (mode == 2) {          // transposed split (V^T)
                __half h, l;
                split2h(v00, h, l);
                Ch[(size_t)c0 * Mrows + r0] = h;       Cl[(size_t)c0 * Mrows + r0] = l;
                split2h(v01, h, l);
                Ch[(size_t)(c0 + 1) * Mrows + r0] = h; Cl[(size_t)(c0 + 1) * Mrows + r0] = l;
                split2h(v10, h, l);
                Ch[(size_t)c0 * Mrows + r0 + 8] = h;   Cl[(size_t)c0 * Mrows + r0 + 8] = l;
                split2h(v11, h, l);
                Ch[(size_t)(c0 + 1) * Mrows + r0 + 8] = h;
                Cl[(size_t)(c0 + 1) * Mrows + r0 + 8] = l;
            } else {                         // mode 3: fp16 hi only
                *(__half2*)(Ch + (size_t)r0 * Ncols + c0) =
                    __halves2half2(__float2half_rn(v00), __float2half_rn(v01));
                *(__half2*)(Ch + (size_t)(r0 + 8) * Ncols + c0) =
                    __halves2half2(__float2half_rn(v10), __float2half_rn(v11));
            }
        }
    }
}

// ---------------------------------------------------------------------------
// fp32 -> fp16 cast (A-side tensors)
// ---------------------------------------------------------------------------
__global__ __launch_bounds__(256)
void cast_f32_f16(const float* __restrict__ x, __half* __restrict__ h, size_t n)
{
    size_t i = (size_t)blockIdx.x * 256 + threadIdx.x;
    size_t stride = (size_t)gridDim.x * 256;
    for (; i < n; i += stride) h[i] = __float2half_rn(x[i]);
}

// fused (hi,lo) split of the four MFxMF weight matrices
__global__ __launch_bounds__(256)
void split_w4(const float* __restrict__ w0, __half* __restrict__ h0, __half* __restrict__ l0,
              const float* __restrict__ w1, __half* __restrict__ h1, __half* __restrict__ l1,
              const float* __restrict__ w2, __half* __restrict__ h2, __half* __restrict__ l2,
              const float* __restrict__ w3, __half* __restrict__ h3, __half* __restrict__ l3)
{
    const size_t n = (size_t)MF * MF;
    size_t i = (size_t)blockIdx.x * 256 + threadIdx.x;
    size_t stride = (size_t)gridDim.x * 256;
    for (; i < n; i += stride) {
        float v; __half hb, lb;
        v = w0[i]; split2h(v, hb, lb); h0[i] = hb; l0[i] = lb;
        v = w1[i]; split2h(v, hb, lb); h1[i] = hb; l1[i] = lb;
        v = w2[i]; split2h(v, hb, lb); h2[i] = hb; l2[i] = lb;
        v = w3[i]; split2h(v, hb, lb); h3[i] = hb; l3[i] = lb;
    }
}

// ---------------------------------------------------------------------------
// Row softmax + dropout mask -> fp16  (MUST run with 256 threads)
// ---------------------------------------------------------------------------
#define SMX_T 256
__global__ __launch_bounds__(SMX_T)
void softmax_dropout_h(const float* __restrict__ S, const float* __restrict__ u,
                       __half* __restrict__ Sh)
{
    __shared__ float row[NF];
    __shared__ float red[SMX_T];

    const int r = blockIdx.x;
    const int tid = threadIdx.x;
    const float* Srow = S + (size_t)r * NF;
    const float* urow = u + (size_t)r * NF;
    const size_t base = (size_t)r * NF;

    float lmax = -INFINITY;
    for (int c = tid; c < NF; c += SMX_T) {
        float v = Srow[c];
        row[c] = v;
        lmax = fmaxf(lmax, v);
    }
    red[tid] = lmax;
    __syncthreads();
    #pragma unroll
    for (int s = SMX_T / 2; s > 0; s >>= 1) {
        if (tid < s) red[tid] = fmaxf(red[tid], red[tid + s]);
        __syncthreads();
    }
    const float m = red[0];
    __syncthreads();

    float lsum = 0.0f;
    for (int c = tid; c < NF; c += SMX_T) {
        float e = __expf(row[c] - m);
        row[c] = e;
        lsum += e;
    }
    red[tid] = lsum;
    __syncthreads();
    #pragma unroll
    for (int s = SMX_T / 2; s > 0; s >>= 1) {
        if (tid < s) red[tid] += red[tid + s];
        __syncthreads();
    }
    const float inv = 1.0f / red[0];

    for (int c = tid; c < NF; c += SMX_T) {
        float keep = (urow[c] >= 0.5f) ? 2.0f : 0.0f;
        Sh[base + c] = __float2half_rn(row[c] * inv * keep);
    }
}

// ---------------------------------------------------------------------------
// Launch
// ---------------------------------------------------------------------------
extern "C" void kernel_launch(void* const* d_in, const int* in_sizes, int n_in,
                              void* d_out, int out_size)
{
    const float* x  = (const float*)d_in[0];
    const float* Wk = (const float*)d_in[1];
    const float* Wq = (const float*)d_in[2];
    const float* Wv = (const float*)d_in[3];
    const float* Wo = (const float*)d_in[4];
    const float* u  = (const float*)d_in[5];
    float* out = (float*)d_out;

    cudaFuncSetAttribute(gemm_mma, cudaFuncAttributeMaxDynamicSharedMemorySize,
                         DYN_SMEM);

    float* S;
    __half *xh, *Wkh, *Wkl, *Wqh, *Wql, *Wvh, *Wvl, *Woh, *Wol;
    __half *Kh, *Kl, *Qh, *Vth, *Vtl, *Sh, *Yh;
    cudaGetSymbolAddress((void**)&S, g_S);
    cudaGetSymbolAddress((void**)&xh, g_xh);
    cudaGetSymbolAddress((void**)&Wkh, g_Wkh); cudaGetSymbolAddress((void**)&Wkl, g_Wkl);
    cudaGetSymbolAddress((void**)&Wqh, g_Wqh); cudaGetSymbolAddress((void**)&Wql, g_Wql);
    cudaGetSymbolAddress((void**)&Wvh, g_Wvh); cudaGetSymbolAddress((void**)&Wvl, g_Wvl);
    cudaGetSymbolAddress((void**)&Woh, g_Woh); cudaGetSymbolAddress((void**)&Wol, g_Wol);
    cudaGetSymbolAddress((void**)&Kh, g_Kh);   cudaGetSymbolAddress((void**)&Kl, g_Kl);
    cudaGetSymbolAddress((void**)&Qh, g_Qh);
    cudaGetSymbolAddress((void**)&Vth, g_Vth); cudaGetSymbolAddress((void**)&Vtl, g_Vtl);
    cudaGetSymbolAddress((void**)&Sh, g_Sh);
    cudaGetSymbolAddress((void**)&Yh, g_Yh);

    // 1) conversions
    cast_f32_f16<<<4096, 256>>>(x, xh, (size_t)NF * MF);             // launch 0
    split_w4<<<1024, 256>>>(Wk, Wkh, Wkl, Wq, Wqh, Wql,
                            Wv, Wvh, Wvl, Wo, Woh, Wol);             // launch 1

    const dim3 gemmBlk(128);
    const dim3 gProj(MF / BN, NF / BM);   // (8, 64)
    const dim3 gAttn(NF / BN, NF / BM);   // (64, 64)

    // 2) projections
    gemm_mma<<<gProj, gemmBlk, DYN_SMEM>>>(xh, Wkh, Wkl, nullptr, Kh, Kl,
                                           NF, MF, MF, 1.0f, 1);     // launch 2
    gemm_mma<<<gProj, gemmBlk, DYN_SMEM>>>(xh, Wqh, Wql, nullptr, Qh, nullptr,
                                           NF, MF, MF, 0.06f, 3);    // launch 3
    gemm_mma<<<gProj, gemmBlk, DYN_SMEM>>>(xh, Wvh, Wvl, nullptr, Vth, Vtl,
                                           NF, MF, MF, 1.0f, 2);     // launch 4

    // 3) logits S = Q K^T (fp32) — launch 5 for ncu (big GEMM)
    gemm_mma<<<gAttn, gemmBlk, DYN_SMEM>>>(Qh, Kh, Kl, S, nullptr, nullptr,
                                           NF, NF, MF, 1.0f, 0);

    // 4) softmax + dropout -> fp16 (256 threads — kernel requires it)
    softmax_dropout_h<<<NF, SMX_T>>>(S, u, Sh);

    // 5) Y = W V
    gemm_mma<<<gProj, gemmBlk, DYN_SMEM>>>(Sh, Vth, Vtl, nullptr, Yh, nullptr,
                                           NF, MF, NF, 1.0f, 3);

    // 6) out = Y Wo^T (fp32)
    gemm_mma<<<gProj, gemmBlk, DYN_SMEM>>>(Yh, Woh, Wol, out, nullptr, nullptr,
                                           NF, MF, MF, 1.0f, 0);
}

// round 11
// speedup vs baseline: 4.2937x; 1.1645x over previous
#include <cuda_runtime.h>
#include <cuda_fp16.h>
#include <cstdint>
#include <math.h>

// ---------------------------------------------------------------------------
// SelfAttention via split-fp16 HMMA (mma.sync m16n8k16.f32.f16.f16.f32).
// out = softmax((x Wq^T * 0.06)(x Wk^T)^T)*dropmask @ (x Wv^T) @ Wo^T
// N = 8192, M = 1024.
// Precision: B split (Bh+Bl fp16), A fp16 hi-only. C = Ah*Bh + Ah*Bl.
// R11: CTA 128x64, warp 64x32, 3 CTAs/SM (12 warps), whole-chunk fragment
//      prefetch -> longer uninterrupted MMA bursts.
// ---------------------------------------------------------------------------

#define NF 8192
#define MF 1024

// ---------------- scratch (__device__ globals) ------------------------------
__device__ float  g_S [(size_t)NF * NF];                 // 256 MB logits
__device__ __half g_Sh[(size_t)NF * NF];                 // 128 MB (A side)
__device__ __half g_xh[(size_t)NF * MF];
__device__ __half g_Wkh[(size_t)MF * MF], g_Wkl[(size_t)MF * MF];
__device__ __half g_Wqh[(size_t)MF * MF], g_Wql[(size_t)MF * MF];
__device__ __half g_Wvh[(size_t)MF * MF], g_Wvl[(size_t)MF * MF];
__device__ __half g_Woh[(size_t)MF * MF], g_Wol[(size_t)MF * MF];
__device__ __half g_Kh[(size_t)NF * MF], g_Kl[(size_t)NF * MF];
__device__ __half g_Qh[(size_t)NF * MF];
__device__ __half g_Vth[(size_t)MF * NF], g_Vtl[(size_t)MF * NF]; // V^T
__device__ __half g_Yh[(size_t)NF * MF];

// ---------------- tile config ----------------------------------------------
#define BM 128
#define BN 64
#define BKE 32                    // K elems per chunk (fp16)
#define RS 40                     // smem row stride in elems (80 B)
#define OFF_A  0                          // A: 128 rows x 80B = 10240
#define OFF_BH (BM * RS * 2)              // Bh: 64 rows x 80B = 5120
#define OFF_BL (BM * RS * 2 + BN * RS * 2)
#define STAGE_B ((BM + 2 * BN) * RS * 2)  // 20480
#define NSTAGE 3
#define DYN_SMEM (NSTAGE * STAGE_B)       // 61440/CTA (3 CTAs -> 180 KB/SM)

// ---------------- PTX helpers ----------------------------------------------
__device__ __forceinline__ uint32_t s2u(const void* p) {
    uint32_t a;
    asm("{ .reg .u64 t; cvta.to.shared.u64 t, %1; cvt.u32.u64 %0, t; }"
        : "=r"(a) : "l"(p));
    return a;
}
__device__ __forceinline__ void cpa16(uint32_t dst, const void* src) {
    asm volatile("cp.async.cg.shared.global [%0], [%1], 16;"
                 :: "r"(dst), "l"(src) : "memory");
}
__device__ __forceinline__ void ldsm4(uint32_t* r, uint32_t addr) {
    asm volatile("ldmatrix.sync.aligned.m8n8.x4.shared.b16 {%0,%1,%2,%3}, [%4];"
                 : "=r"(r[0]), "=r"(r[1]), "=r"(r[2]), "=r"(r[3]) : "r"(addr));
}
__device__ __forceinline__ void mma16816(float* c, const uint32_t* a,
                                         const uint32_t* b) {
    asm volatile(
        "mma.sync.aligned.m16n8k16.row.col.f32.f16.f16.f32 "
        "{%0,%1,%2,%3}, {%4,%5,%6,%7}, {%8,%9}, {%0,%1,%2,%3};"
        : "+f"(c[0]), "+f"(c[1]), "+f"(c[2]), "+f"(c[3])
        : "r"(a[0]), "r"(a[1]), "r"(a[2]), "r"(a[3]), "r"(b[0]), "r"(b[1]));
}
__device__ __forceinline__ void split2h(float v, __half& h, __half& l) {
    h = __float2half_rn(v);
    l = __float2half_rn(v - __half2float(h));
}

// ---------------------------------------------------------------------------
// NT GEMM: C[M,N] = alpha * Ah[M,K] * ((Bh+Bl)[N,K])^T   (2 MMA passes)
// mode 0: fp32 out. mode 1: split fp16 out. mode 2: split fp16 transposed.
// mode 3: fp16 hi-only out. Requires M mult 128, N mult 64, K mult 32.
// ---------------------------------------------------------------------------
__global__ __launch_bounds__(128, 3)
void gemm_mma(const __half* __restrict__ Ah,
              const __half* __restrict__ Bh, const __half* __restrict__ Bl,
              float* __restrict__ Cf,
              __half* __restrict__ Ch, __half* __restrict__ Cl,
              int Mrows, int Ncols, int Kdim, float alpha, int mode)
{
    extern __shared__ char dynraw[];
    const uint32_t sbase = s2u(dynraw);

    const int tid  = threadIdx.x;
    const int wid  = tid >> 5;
    const int lane = tid & 31;
    const int bx = blockIdx.x, by = blockIdx.y;

    const int wmBase = (wid & 1) * 64;      // warp M origin (0,64)
    const int wnBase = (wid >> 1) * 32;     // warp N origin (0,32)

    const size_t rowA0 = (size_t)by * BM;
    const size_t rowB0 = (size_t)bx * BN;

    // loader: A 128 rows, Bh/Bl 64 rows; 4 x 16B per row
    auto load_chunk = [&](int kc, int stg) {
        const int k0 = kc * BKE;
        const uint32_t sb = sbase + stg * STAGE_B;
        #pragma unroll
        for (int i = 0; i < 4; i++) {                  // A: 512 x 16B
            const int idx = tid + i * 128;
            const int r = idx >> 2, c = idx & 3;
            const uint32_t so = (uint32_t)(r * RS * 2 + c * 16);
            cpa16(sb + OFF_A + so, Ah + (rowA0 + r) * (size_t)Kdim + k0 + c * 8);
        }
        #pragma unroll
        for (int i = 0; i < 2; i++) {                  // B: 256 x 16B each
            const int idx = tid + i * 128;
            const int r = idx >> 2, c = idx & 3;
            const uint32_t so = (uint32_t)(r * RS * 2 + c * 16);
            const size_t gb = (rowB0 + r) * (size_t)Kdim + k0 + c * 8;
            cpa16(sb + OFF_BH + so, Bh + gb);
            cpa16(sb + OFF_BL + so, Bl + gb);
        }
        asm volatile("cp.async.commit_group;" ::: "memory");
    };

    float acc[4][4][4];
    #pragma unroll
    for (int i = 0; i < 4; i++)
        #pragma unroll
        for (int j = 0; j < 4; j++)
            #pragma unroll
            for (int k = 0; k < 4; k++) acc[i][j][k] = 0.0f;

    const int nchunks = Kdim / BKE;

    const int q  = lane >> 3;
    const int r8 = lane & 7;
    const int aRowOff = ((q & 1) ? 8 : 0) + r8;
    const int aKOff   = ((q >> 1) ? 8 : 0);
    const int bRowOff = ((q >> 1) ? 8 : 0) + r8;
    const int bKOff   = ((q & 1) ? 8 : 0);

    load_chunk(0, 0);
    if (nchunks > 1) load_chunk(1, 1);

    for (int kc = 0; kc < nchunks; kc++) {
        if (kc + 1 < nchunks) {
            asm volatile("cp.async.wait_group 1;" ::: "memory");
        } else {
            asm volatile("cp.async.wait_group 0;" ::: "memory");
        }
        __syncthreads();

        if (kc + 2 < nchunks) load_chunk(kc + 2, (kc + 2) % NSTAGE);

        const uint32_t sb = sbase + (kc % NSTAGE) * STAGE_B;

        // ---- prefetch ALL fragments for the whole 32-K chunk (both ks) ----
        uint32_t ah[2][4][4], bh[2][2][4], bl[2][2][4];
        #pragma unroll
        for (int ks = 0; ks < 2; ks++) {
            #pragma unroll
            for (int am = 0; am < 4; am++) {
                const uint32_t off =
                    (uint32_t)((wmBase + am * 16 + aRowOff) * RS
                               + ks * 16 + aKOff) * 2;
                ldsm4(ah[ks][am], sb + OFF_A + off);
            }
            #pragma unroll
            for (int j = 0; j < 2; j++) {
                const uint32_t off =
                    (uint32_t)((wnBase + j * 16 + bRowOff) * RS
                               + ks * 16 + bKOff) * 2;
                ldsm4(bh[ks][j], sb + OFF_BH + off);
                ldsm4(bl[ks][j], sb + OFF_BL + off);
            }
        }
        // ---- one long MMA burst: 64 MMAs, acc reuse distance 8 ----------
        #pragma unroll
        for (int ks = 0; ks < 2; ks++) {
            #pragma unroll
            for (int j = 0; j < 2; j++)
                #pragma unroll
                for (int am = 0; am < 4; am++) {
                    mma16816(acc[am][j * 2],     ah[ks][am], bh[ks][j]);
                    mma16816(acc[am][j * 2 + 1], ah[ks][am], bh[ks][j] + 2);
                }
            #pragma unroll
            for (int j = 0; j < 2; j++)
                #pragma unroll
                for (int am = 0; am < 4; am++) {
                    mma16816(acc[am][j * 2],     ah[ks][am], bl[ks][j]);
                    mma16816(acc[am][j * 2 + 1], ah[ks][am], bl[ks][j] + 2);
                }
        }
    }

    // ---------------- epilogue --------------------------------------------
    #pragma unroll
    for (int am = 0; am < 4; am++) {
        const int r0 = by * BM + wmBase + am * 16 + (lane >> 2);
        #pragma unroll
        for (int an = 0; an < 4; an++) {
            const int c0 = bx * BN + wnBase + an * 8 + (lane & 3) * 2;
            const float v00 = alpha * acc[am][an][0];
            const float v01 = alpha * acc[am][an][1];
            const float v10 = alpha * acc[am][an][2];
            const float v11 = alpha * acc[am][an][3];
            if (mode == 0) {
                *(float2*)(Cf + (size_t)r0 * Ncols + c0)       = make_float2(v00, v01);
                *(float2*)(Cf + (size_t)(r0 + 8) * Ncols + c0) = make_float2(v10, v11);
            } else if (mode == 1) {
                __half h0, l0, h1, l1;
                split2h(v00, h0, l0); split2h(v01, h1, l1);
                *(__half2*)(Ch + (size_t)r0 * Ncols + c0) = __halves2half2(h0, h1);
                *(__half2*)(Cl + (size_t)r0 * Ncols + c0) = __halves2half2(l0, l1);
                split2h(v10, h0, l0); split2h(v11, h1, l1);
                *(__half2*)(Ch + (size_t)(r0 + 8) * Ncols + c0) = __halves2half2(h0, h1);
                *(__half2*)(Cl + (size_t)(r0 + 8) * Ncols + c0) = __halves2half2(l0, l1);
            } else if (mode == 2) {          // transposed split (V^T)
                __half h, l;
                split2h(v00, h, l);
                Ch[(size_t)c0 * Mrows + r0] = h;       Cl[(size_t)c0 * Mrows + r0] = l;
                split2h(v01, h, l);
                Ch[(size_t)(c0 + 1) * Mrows + r0] = h; Cl[(size_t)(c0 + 1) * Mrows + r0] = l;
                split2h(v10, h, l);
                Ch[(size_t)c0 * Mrows + r0 + 8] = h;   Cl[(size_t)c0 * Mrows + r0 + 8] = l;
                split2h(v11, h, l);
                Ch[(size_t)(c0 + 1) * Mrows + r0 + 8] = h;
                Cl[(size_t)(c0 + 1) * Mrows + r0 + 8] = l;
            } else {                         // mode 3: fp16 hi only
                *(__half2*)(Ch + (size_t)r0 * Ncols + c0) =
                    __halves2half2(__float2half_rn(v00), __float2half_rn(v01));
                *(__half2*)(Ch + (size_t)(r0 + 8) * Ncols + c0) =
                    __halves2half2(__float2half_rn(v10), __float2half_rn(v11));
            }
        }
    }
}

// ---------------------------------------------------------------------------
// fp32 -> fp16 cast (A-side tensors)
// ---------------------------------------------------------------------------
__global__ __launch_bounds__(256)
void cast_f32_f16(const float* __restrict__ x, __half* __restrict__ h, size_t n)
{
    size_t i = (size_t)blockIdx.x * 256 + threadIdx.x;
    size_t stride = (size_t)gridDim.x * 256;
    for (; i < n; i += stride) h[i] = __float2half_rn(x[i]);
}

// fused (hi,lo) split of the four MFxMF weight matrices
__global__ __launch_bounds__(256)
void split_w4(const float* __restrict__ w0, __half* __restrict__ h0, __half* __restrict__ l0,
              const float* __restrict__ w1, __half* __restrict__ h1, __half* __restrict__ l1,
              const float* __restrict__ w2, __half* __restrict__ h2, __half* __restrict__ l2,
              const float* __restrict__ w3, __half* __restrict__ h3, __half* __restrict__ l3)
{
    const size_t n = (size_t)MF * MF;
    size_t i = (size_t)blockIdx.x * 256 + threadIdx.x;
    size_t stride = (size_t)gridDim.x * 256;
    for (; i < n; i += stride) {
        float v; __half hb, lb;
        v = w0[i]; split2h(v, hb, lb); h0[i] = hb; l0[i] = lb;
        v = w1[i]; split2h(v, hb, lb); h1[i] = hb; l1[i] = lb;
        v = w2[i]; split2h(v, hb, lb); h2[i] = hb; l2[i] = lb;
        v = w3[i]; split2h(v, hb, lb); h3[i] = hb; l3[i] = lb;
    }
}

// ---------------------------------------------------------------------------
// Row softmax + dropout mask -> fp16  (MUST run with SMX_T threads)
// ---------------------------------------------------------------------------
#define SMX_T 256
__global__ __launch_bounds__(SMX_T)
void softmax_dropout_h(const float* __restrict__ S, const float* __restrict__ u,
                       __half* __restrict__ Sh)
{
    __shared__ float row[NF];
    __shared__ float red[SMX_T];

    const int r = blockIdx.x;
    const int tid = threadIdx.x;
    const float* Srow = S + (size_t)r * NF;
    const float* urow = u + (size_t)r * NF;
    const size_t base = (size_t)r * NF;

    float lmax = -INFINITY;
    for (int c = tid; c < NF; c += SMX_T) {
        float v = Srow[c];
        row[c] = v;
        lmax = fmaxf(lmax, v);
    }
    red[tid] = lmax;
    __syncthreads();
    #pragma unroll
    for (int s = SMX_T / 2; s > 0; s >>= 1) {
        if (tid < s) red[tid] = fmaxf(red[tid], red[tid + s]);
        __syncthreads();
    }
    const float m = red[0];
    __syncthreads();

    float lsum = 0.0f;
    for (int c = tid; c < NF; c += SMX_T) {
        float e = __expf(row[c] - m);
        row[c] = e;
        lsum += e;
    }
    red[tid] = lsum;
    __syncthreads();
    #pragma unroll
    for (int s = SMX_T / 2; s > 0; s >>= 1) {
        if (tid < s) red[tid] += red[tid + s];
        __syncthreads();
    }
    const float inv = 1.0f / red[0];

    for (int c = tid; c < NF; c += SMX_T) {
        float keep = (urow[c] >= 0.5f) ? 2.0f : 0.0f;
        Sh[base + c] = __float2half_rn(row[c] * inv * keep);
    }
}

// ---------------------------------------------------------------------------
// Launch
// ---------------------------------------------------------------------------
extern "C" void kernel_launch(void* const* d_in, const int* in_sizes, int n_in,
                              void* d_out, int out_size)
{
    const float* x  = (const float*)d_in[0];
    const float* Wk = (const float*)d_in[1];
    const float* Wq = (const float*)d_in[2];
    const float* Wv = (const float*)d_in[3];
    const float* Wo = (const float*)d_in[4];
    const float* u  = (const float*)d_in[5];
    float* out = (float*)d_out;

    cudaFuncSetAttribute(gemm_mma, cudaFuncAttributeMaxDynamicSharedMemorySize,
                         DYN_SMEM);

    float* S;
    __half *xh, *Wkh, *Wkl, *Wqh, *Wql, *Wvh, *Wvl, *Woh, *Wol;
    __half *Kh, *Kl, *Qh, *Vth, *Vtl, *Sh, *Yh;
    cudaGetSymbolAddress((void**)&S, g_S);
    cudaGetSymbolAddress((void**)&xh, g_xh);
    cudaGetSymbolAddress((void**)&Wkh, g_Wkh); cudaGetSymbolAddress((void**)&Wkl, g_Wkl);
    cudaGetSymbolAddress((void**)&Wqh, g_Wqh); cudaGetSymbolAddress((void**)&Wql, g_Wql);
    cudaGetSymbolAddress((void**)&Wvh, g_Wvh); cudaGetSymbolAddress((void**)&Wvl, g_Wvl);
    cudaGetSymbolAddress((void**)&Woh, g_Woh); cudaGetSymbolAddress((void**)&Wol, g_Wol);
    cudaGetSymbolAddress((void**)&Kh, g_Kh);   cudaGetSymbolAddress((void**)&Kl, g_Kl);
    cudaGetSymbolAddress((void**)&Qh, g_Qh);
    cudaGetSymbolAddress((void**)&Vth, g_Vth); cudaGetSymbolAddress((void**)&Vtl, g_Vtl);
    cudaGetSymbolAddress((void**)&Sh, g_Sh);
    cudaGetSymbolAddress((void**)&Yh, g_Yh);

    // 1) conversions
    cast_f32_f16<<<4096, 256>>>(x, xh, (size_t)NF * MF);             // launch 0
    split_w4<<<1024, 256>>>(Wk, Wkh, Wkl, Wq, Wqh, Wql,
                            Wv, Wvh, Wvl, Wo, Woh, Wol);             // launch 1

    const dim3 gemmBlk(128);
    const dim3 gProj(MF / BN, NF / BM);   // (16, 64)
    const dim3 gAttn(NF / BN, NF / BM);   // (128, 64)

    // 2) projections
    gemm_mma<<<gProj, gemmBlk, DYN_SMEM>>>(xh, Wkh, Wkl, nullptr, Kh, Kl,
                                           NF, MF, MF, 1.0f, 1);     // launch 2
    gemm_mma<<<gProj, gemmBlk, DYN_SMEM>>>(xh, Wqh, Wql, nullptr, Qh, nullptr,
                                           NF, MF, MF, 0.06f, 3);    // launch 3
    gemm_mma<<<gProj, gemmBlk, DYN_SMEM>>>(xh, Wvh, Wvl, nullptr, Vth, Vtl,
                                           NF, MF, MF, 1.0f, 2);     // launch 4

    // 3) logits S = Q K^T (fp32) — launch 5 for ncu (big GEMM)
    gemm_mma<<<gAttn, gemmBlk, DYN_SMEM>>>(Qh, Kh, Kl, S, nullptr, nullptr,
                                           NF, NF, MF, 1.0f, 0);

    // 4) softmax + dropout -> fp16
    softmax_dropout_h<<<NF, SMX_T>>>(S, u, Sh);

    // 5) Y = W V
    gemm_mma<<<gProj, gemmBlk, DYN_SMEM>>>(Sh, Vth, Vtl, nullptr, Yh, nullptr,
                                           NF, MF, NF, 1.0f, 3);

    // 6) out = Y Wo^T (fp32)
    gemm_mma<<<gProj, gemmBlk, DYN_SMEM>>>(Yh, Woh, Wol, out, nullptr, nullptr,
                                           NF, MF, MF, 1.0f, 0);
}

// round 13
// speedup vs baseline: 4.6653x; 1.0865x over previous
#include <cuda_runtime.h>
#include <cuda_fp16.h>
#include <cstdint>
#include <math.h>

// ---------------------------------------------------------------------------
// SelfAttention via split-fp16 HMMA (mma.sync m16n8k16.f32.f16.f16.f32).
// out = softmax((x Wq^T * 0.06)(x Wk^T)^T)*dropmask @ (x Wv^T) @ Wo^T
// N = 8192, M = 1024.
// Precision: B split (Bh+Bl fp16), A fp16 hi-only. C = Ah*Bh + Ah*Bl.
// R13: R12 fragment double-buffering with CORRECT cp.async protocol:
//      wait_group THEN __syncthreads before any cross-warp tile read
//      (cp.async completion is per-warp; R12 had sync before wait = race).
//      Tail uses wait_group 0 (wait_group 1 is a no-op when pending == 1).
// ---------------------------------------------------------------------------

#define NF 8192
#define MF 1024

// ---------------- scratch (__device__ globals) ------------------------------
__device__ float  g_S [(size_t)NF * NF];                 // 256 MB logits
__device__ __half g_Sh[(size_t)NF * NF];                 // 128 MB (A side)
__device__ __half g_xh[(size_t)NF * MF];
__device__ __half g_Wkh[(size_t)MF * MF], g_Wkl[(size_t)MF * MF];
__device__ __half g_Wqh[(size_t)MF * MF], g_Wql[(size_t)MF * MF];
__device__ __half g_Wvh[(size_t)MF * MF], g_Wvl[(size_t)MF * MF];
__device__ __half g_Woh[(size_t)MF * MF], g_Wol[(size_t)MF * MF];
__device__ __half g_Kh[(size_t)NF * MF], g_Kl[(size_t)NF * MF];
__device__ __half g_Qh[(size_t)NF * MF];
__device__ __half g_Vth[(size_t)MF * NF], g_Vtl[(size_t)MF * NF]; // V^T
__device__ __half g_Yh[(size_t)NF * MF];

// ---------------- tile config ----------------------------------------------
#define BM 128
#define BN 64
#define BKE 32                    // K elems per chunk (fp16)
#define RS 40                     // smem row stride in elems (80 B)
#define OFF_A  0                          // A: 128 rows x 80B = 10240
#define OFF_BH (BM * RS * 2)              // Bh: 64 rows x 80B = 5120
#define OFF_BL (BM * RS * 2 + BN * RS * 2)
#define STAGE_B ((BM + 2 * BN) * RS * 2)  // 20480
#define NSTAGE 3
#define DYN_SMEM (NSTAGE * STAGE_B)       // 61440/CTA (3 CTAs -> 180 KB/SM)

// ---------------- PTX helpers ----------------------------------------------
__device__ __forceinline__ uint32_t s2u(const void* p) {
    uint32_t a;
    asm("{ .reg .u64 t; cvta.to.shared.u64 t, %1; cvt.u32.u64 %0, t; }"
        : "=r"(a) : "l"(p));
    return a;
}
__device__ __forceinline__ void cpa16(uint32_t dst, const void* src) {
    asm volatile("cp.async.cg.shared.global [%0], [%1], 16;"
                 :: "r"(dst), "l"(src) : "memory");
}
__device__ __forceinline__ void ldsm4(uint32_t* r, uint32_t addr) {
    asm volatile("ldmatrix.sync.aligned.m8n8.x4.shared.b16 {%0,%1,%2,%3}, [%4];"
                 : "=r"(r[0]), "=r"(r[1]), "=r"(r[2]), "=r"(r[3]) : "r"(addr));
}
__device__ __forceinline__ void mma16816(float* c, const uint32_t* a,
                                         const uint32_t* b) {
    asm volatile(
        "mma.sync.aligned.m16n8k16.row.col.f32.f16.f16.f32 "
        "{%0,%1,%2,%3}, {%4,%5,%6,%7}, {%8,%9}, {%0,%1,%2,%3};"
        : "+f"(c[0]), "+f"(c[1]), "+f"(c[2]), "+f"(c[3])
        : "r"(a[0]), "r"(a[1]), "r"(a[2]), "r"(a[3]), "r"(b[0]), "r"(b[1]));
}
__device__ __forceinline__ void split2h(float v, __half& h, __half& l) {
    h = __float2half_rn(v);
    l = __float2half_rn(v - __half2float(h));
}

// ---------------------------------------------------------------------------
// NT GEMM: C[M,N] = alpha * Ah[M,K] * ((Bh+Bl)[N,K])^T   (2 MMA passes)
// mode 0: fp32 out. mode 1: split fp16 out. mode 2: split fp16 transposed.
// mode 3: fp16 hi-only out. Requires M mult 128, N mult 64, K mult 32.
// ---------------------------------------------------------------------------
__global__ __launch_bounds__(128, 3)
void gemm_mma(const __half* __restrict__ Ah,
              const __half* __restrict__ Bh, const __half* __restrict__ Bl,
              float* __restrict__ Cf,
              __half* __restrict__ Ch, __half* __restrict__ Cl,
              int Mrows, int Ncols, int Kdim, float alpha, int mode)
{
    extern __shared__ char dynraw[];
    const uint32_t sbase = s2u(dynraw);

    const int tid  = threadIdx.x;
    const int wid  = tid >> 5;
    const int lane = tid & 31;
    const int bx = blockIdx.x, by = blockIdx.y;

    const int wmBase = (wid & 1) * 64;      // warp M origin (0,64)
    const int wnBase = (wid >> 1) * 32;     // warp N origin (0,32)

    const size_t rowA0 = (size_t)by * BM;
    const size_t rowB0 = (size_t)bx * BN;

    auto load_chunk = [&](int kc, int stg) {
        const int k0 = kc * BKE;
        const uint32_t sb = sbase + stg * STAGE_B;
        #pragma unroll
        for (int i = 0; i < 4; i++) {                  // A: 512 x 16B
            const int idx = tid + i * 128;
            const int r = idx >> 2, c = idx & 3;
            const uint32_t so = (uint32_t)(r * RS * 2 + c * 16);
            cpa16(sb + OFF_A + so, Ah + (rowA0 + r) * (size_t)Kdim + k0 + c * 8);
        }
        #pragma unroll
        for (int i = 0; i < 2; i++) {                  // B: 256 x 16B each
            const int idx = tid + i * 128;
            const int r = idx >> 2, c = idx & 3;
            const uint32_t so = (uint32_t)(r * RS * 2 + c * 16);
            const size_t gb = (rowB0 + r) * (size_t)Kdim + k0 + c * 8;
            cpa16(sb + OFF_BH + so, Bh + gb);
            cpa16(sb + OFF_BL + so, Bl + gb);
        }
        asm volatile("cp.async.commit_group;" ::: "memory");
    };

    float acc[4][4][4];
    #pragma unroll
    for (int i = 0; i < 4; i++)
        #pragma unroll
        for (int j = 0; j < 4; j++)
            #pragma unroll
            for (int k = 0; k < 4; k++) acc[i][j][k] = 0.0f;

    const int nchunks = Kdim / BKE;

    const int q  = lane >> 3;
    const int r8 = lane & 7;
    const int aRowOff = ((q & 1) ? 8 : 0) + r8;
    const int aKOff   = ((q >> 1) ? 8 : 0);
    const int bRowOff = ((q >> 1) ? 8 : 0) + r8;
    const int bKOff   = ((q & 1) ? 8 : 0);

    // two fragment buffers: buf 0 <-> ks=0, buf 1 <-> ks=1
    uint32_t fa[2][4][4], fbh[2][2][4], fbl[2][2][4];

    auto ldfrag = [&](int buf, uint32_t sb, int ks) {
        #pragma unroll
        for (int am = 0; am < 4; am++) {
            const uint32_t off =
                (uint32_t)((wmBase + am * 16 + aRowOff) * RS
                           + ks * 16 + aKOff) * 2;
            ldsm4(fa[buf][am], sb + OFF_A + off);
        }
        #pragma unroll
        for (int j = 0; j < 2; j++) {
            const uint32_t off =
                (uint32_t)((wnBase + j * 16 + bRowOff) * RS
                           + ks * 16 + bKOff) * 2;
            ldsm4(fbh[buf][j], sb + OFF_BH + off);
            ldsm4(fbl[buf][j], sb + OFF_BL + off);
        }
    };
    auto do_mma = [&](int buf) {
        #pragma unroll
        for (int j = 0; j < 2; j++)
            #pragma unroll
            for (int am = 0; am < 4; am++) {
                mma16816(acc[am][j * 2],     fa[buf][am], fbh[buf][j]);
                mma16816(acc[am][j * 2 + 1], fa[buf][am], fbh[buf][j] + 2);
            }
        #pragma unroll
        for (int j = 0; j < 2; j++)
            #pragma unroll
            for (int am = 0; am < 4; am++) {
                mma16816(acc[am][j * 2],     fa[buf][am], fbl[buf][j]);
                mma16816(acc[am][j * 2 + 1], fa[buf][am], fbl[buf][j] + 2);
            }
    };

    // prologue: stages 0,1 in flight; chunk 0 globally resident; frag ks0 in
    load_chunk(0, 0);
    if (nchunks > 1) {
        load_chunk(1, 1);
        asm volatile("cp.async.wait_group 1;" ::: "memory");  // own chunk0
    } else {
        asm volatile("cp.async.wait_group 0;" ::: "memory");
    }
    __syncthreads();                                            // ALL chunk0
    ldfrag(0, sbase, 0);

    // invariant at top of iter kc: chunk kc resident globally (barrier of
    // iter kc-1 sealed it); frag buf0 holds (kc, ks0).
    for (int kc = 0; kc < nchunks; kc++) {
        const uint32_t sb_cur = sbase + (kc % NSTAGE) * STAGE_B;
        const uint32_t sb_nxt = sbase + ((kc + 1) % NSTAGE) * STAGE_B;

        // phase A: prefetch (kc, ks1) under MMA of (kc, ks0)
        ldfrag(1, sb_cur, 1);
        do_mma(0);

        // issue load of chunk kc+2; its stage's last readers (chunk kc-1,
        // phase A of iter kc-1) were sealed by iter kc-1's barrier.
        if (kc + 2 < nchunks) {
            load_chunk(kc + 2, (kc + 2) % NSTAGE);
            // pending = {kc+1, kc+2} -> own chunk kc+1 complete
            asm volatile("cp.async.wait_group 1;" ::: "memory");
        } else {
            // tail: pending <= {kc+1}; wait_group 1 would be a no-op
            asm volatile("cp.async.wait_group 0;" ::: "memory");
        }
        __syncthreads();   // chunk kc+1 resident for ALL warps

        // phase B: prefetch (kc+1, ks0) under MMA of (kc, ks1)
        if (kc + 1 < nchunks) ldfrag(0, sb_nxt, 0);
        do_mma(1);
    }

    // ---------------- epilogue --------------------------------------------
    #pragma unroll
    for (int am = 0; am < 4; am++) {
        const int r0 = by * BM + wmBase + am * 16 + (lane >> 2);
        #pragma unroll
        for (int an = 0; an < 4; an++) {
            const int c0 = bx * BN + wnBase + an * 8 + (lane & 3) * 2;
            const float v00 = alpha * acc[am][an][0];
            const float v01 = alpha * acc[am][an][1];
            const float v10 = alpha * acc[am][an][2];
            const float v11 = alpha * acc[am][an][3];
            if (mode == 0) {
                *(float2*)(Cf + (size_t)r0 * Ncols + c0)       = make_float2(v00, v01);
                *(float2*)(Cf + (size_t)(r0 + 8) * Ncols + c0) = make_float2(v10, v11);
            } else if (mode == 1) {
                __half h0, l0, h1, l1;
                split2h(v00, h0, l0); split2h(v01, h1, l1);
                *(__half2*)(Ch + (size_t)r0 * Ncols + c0) = __halves2half2(h0, h1);
                *(__half2*)(Cl + (size_t)r0 * Ncols + c0) = __halves2half2(l0, l1);
                split2h(v10, h0, l0); split2h(v11, h1, l1);
                *(__half2*)(Ch + (size_t)(r0 + 8) * Ncols + c0) = __halves2half2(h0, h1);
                *(__half2*)(Cl + (size_t)(r0 + 8) * Ncols + c0) = __halves2half2(l0, l1);
            } else if (mode == 2) {          // transposed split (V^T)
                __half h, l;
                split2h(v00, h, l);
                Ch[(size_t)c0 * Mrows + r0] = h;       Cl[(size_t)c0 * Mrows + r0] = l;
                split2h(v01, h, l);
                Ch[(size_t)(c0 + 1) * Mrows + r0] = h; Cl[(size_t)(c0 + 1) * Mrows + r0] = l;
                split2h(v10, h, l);
                Ch[(size_t)c0 * Mrows + r0 + 8] = h;   Cl[(size_t)c0 * Mrows + r0 + 8] = l;
                split2h(v11, h, l);
                Ch[(size_t)(c0 + 1) * Mrows + r0 + 8] = h;
                Cl[(size_t)(c0 + 1) * Mrows + r0 + 8] = l;
            } else {                         // mode 3: fp16 hi only
                *(__half2*)(Ch + (size_t)r0 * Ncols + c0) =
                    __halves2half2(__float2half_rn(v00), __float2half_rn(v01));
                *(__half2*)(Ch + (size_t)(r0 + 8) * Ncols + c0) =
                    __halves2half2(__float2half_rn(v10), __float2half_rn(v11));
            }
        }
    }
}

// ---------------------------------------------------------------------------
// fp32 -> fp16 cast (A-side tensors)
// ---------------------------------------------------------------------------
__global__ __launch_bounds__(256)
void cast_f32_f16(const float* __restrict__ x, __half* __restrict__ h, size_t n)
{
    size_t i = (size_t)blockIdx.x * 256 + threadIdx.x;
    size_t stride = (size_t)gridDim.x * 256;
    for (; i < n; i += stride) h[i] = __float2half_rn(x[i]);
}

// fused (hi,lo) split of the four MFxMF weight matrices
__global__ __launch_bounds__(256)
void split_w4(const float* __restrict__ w0, __half* __restrict__ h0, __half* __restrict__ l0,
              const float* __restrict__ w1, __half* __restrict__ h1, __half* __restrict__ l1,
              const float* __restrict__ w2, __half* __restrict__ h2, __half* __restrict__ l2,
              const float* __restrict__ w3, __half* __restrict__ h3, __half* __restrict__ l3)
{
    const size_t n = (size_t)MF * MF;
    size_t i = (size_t)blockIdx.x * 256 + threadIdx.x;
    size_t stride = (size_t)gridDim.x * 256;
    for (; i < n; i += stride) {
        float v; __half hb, lb;
        v = w0[i]; split2h(v, hb, lb); h0[i] = hb; l0[i] = lb;
        v = w1[i]; split2h(v, hb, lb); h1[i] = hb; l1[i] = lb;
        v = w2[i]; split2h(v, hb, lb); h2[i] = hb; l2[i] = lb;
        v = w3[i]; split2h(v, hb, lb); h3[i] = hb; l3[i] = lb;
    }
}

// ---------------------------------------------------------------------------
// Row softmax + dropout mask -> fp16  (MUST run with SMX_T threads)
// ---------------------------------------------------------------------------
#define SMX_T 256
__global__ __launch_bounds__(SMX_T)
void softmax_dropout_h(const float* __restrict__ S, const float* __restrict__ u,
                       __half* __restrict__ Sh)
{
    __shared__ float row[NF];
    __shared__ float red[SMX_T];

    const int r = blockIdx.x;
    const int tid = threadIdx.x;
    const float* Srow = S + (size_t)r * NF;
    const float* urow = u + (size_t)r * NF;
    const size_t base = (size_t)r * NF;

    float lmax = -INFINITY;
    for (int c = tid; c < NF; c += SMX_T) {
        float v = Srow[c];
        row[c] = v;
        lmax = fmaxf(lmax, v);
    }
    red[tid] = lmax;
    __syncthreads();
    #pragma unroll
    for (int s = SMX_T / 2; s > 0; s >>= 1) {
        if (tid < s) red[tid] = fmaxf(red[tid], red[tid + s]);
        __syncthreads();
    }
    const float m = red[0];
    __syncthreads();

    float lsum = 0.0f;
    for (int c = tid; c < NF; c += SMX_T) {
        float e = __expf(row[c] - m);
        row[c] = e;
        lsum += e;
    }
    red[tid] = lsum;
    __syncthreads();
    #pragma unroll
    for (int s = SMX_T / 2; s > 0; s >>= 1) {
        if (tid < s) red[tid] += red[tid + s];
        __syncthreads();
    }
    const float inv = 1.0f / red[0];

    for (int c = tid; c < NF; c += SMX_T) {
        float keep = (urow[c] >= 0.5f) ? 2.0f : 0.0f;
        Sh[base + c] = __float2half_rn(row[c] * inv * keep);
    }
}

// ---------------------------------------------------------------------------
// Launch
// ---------------------------------------------------------------------------
extern "C" void kernel_launch(void* const* d_in, const int* in_sizes, int n_in,
                              void* d_out, int out_size)
{
    const float* x  = (const float*)d_in[0];
    const float* Wk = (const float*)d_in[1];
    const float* Wq = (const float*)d_in[2];
    const float* Wv = (const float*)d_in[3];
    const float* Wo = (const float*)d_in[4];
    const float* u  = (const float*)d_in[5];
    float* out = (float*)d_out;

    cudaFuncSetAttribute(gemm_mma, cudaFuncAttributeMaxDynamicSharedMemorySize,
                         DYN_SMEM);

    float* S;
    __half *xh, *Wkh, *Wkl, *Wqh, *Wql, *Wvh, *Wvl, *Woh, *Wol;
    __half *Kh, *Kl, *Qh, *Vth, *Vtl, *Sh, *Yh;
    cudaGetSymbolAddress((void**)&S, g_S);
    cudaGetSymbolAddress((void**)&xh, g_xh);
    cudaGetSymbolAddress((void**)&Wkh, g_Wkh); cudaGetSymbolAddress((void**)&Wkl, g_Wkl);
    cudaGetSymbolAddress((void**)&Wqh, g_Wqh); cudaGetSymbolAddress((void**)&Wql, g_Wql);
    cudaGetSymbolAddress((void**)&Wvh, g_Wvh); cudaGetSymbolAddress((void**)&Wvl, g_Wvl);
    cudaGetSymbolAddress((void**)&Woh, g_Woh); cudaGetSymbolAddress((void**)&Wol, g_Wol);
    cudaGetSymbolAddress((void**)&Kh, g_Kh);   cudaGetSymbolAddress((void**)&Kl, g_Kl);
    cudaGetSymbolAddress((void**)&Qh, g_Qh);
    cudaGetSymbolAddress((void**)&Vth, g_Vth); cudaGetSymbolAddress((void**)&Vtl, g_Vtl);
    cudaGetSymbolAddress((void**)&Sh, g_Sh);
    cudaGetSymbolAddress((void**)&Yh, g_Yh);

    // 1) conversions
    cast_f32_f16<<<4096, 256>>>(x, xh, (size_t)NF * MF);             // launch 0
    split_w4<<<1024, 256>>>(Wk, Wkh, Wkl, Wq, Wqh, Wql,
                            Wv, Wvh, Wvl, Wo, Woh, Wol);             // launch 1

    const dim3 gemmBlk(128);
    const dim3 gProj(MF / BN, NF / BM);   // (16, 64)
    const dim3 gAttn(NF / BN, NF / BM);   // (128, 64)

    // 2) projections
    gemm_mma<<<gProj, gemmBlk, DYN_SMEM>>>(xh, Wkh, Wkl, nullptr, Kh, Kl,
                                           NF, MF, MF, 1.0f, 1);     // launch 2
    gemm_mma<<<gProj, gemmBlk, DYN_SMEM>>>(xh, Wqh, Wql, nullptr, Qh, nullptr,
                                           NF, MF, MF, 0.06f, 3);    // launch 3
    gemm_mma<<<gProj, gemmBlk, DYN_SMEM>>>(xh, Wvh, Wvl, nullptr, Vth, Vtl,
                                           NF, MF, MF, 1.0f, 2);     // launch 4

    // 3) logits S = Q K^T (fp32) — launch 5 for ncu (big GEMM)
    gemm_mma<<<gAttn, gemmBlk, DYN_SMEM>>>(Qh, Kh, Kl, S, nullptr, nullptr,
                                           NF, NF, MF, 1.0f, 0);

    // 4) softmax + dropout -> fp16
    softmax_dropout_h<<<NF, SMX_T>>>(S, u, Sh);

    // 5) Y = W V
    gemm_mma<<<gProj, gemmBlk, DYN_SMEM>>>(Sh, Vth, Vtl, nullptr, Yh, nullptr,
                                           NF, MF, NF, 1.0f, 3);

    // 6) out = Y Wo^T (fp32)
    gemm_mma<<<gProj, gemmBlk, DYN_SMEM>>>(Yh, Woh, Wol, out, nullptr, nullptr,
                                           NF, MF, MF, 1.0f, 0);
}

// round 14
// speedup vs baseline: 5.1402x; 1.1018x over previous
#include <cuda_runtime.h>
#include <cuda_fp16.h>
#include <cstdint>
#include <math.h>

// ---------------------------------------------------------------------------
// SelfAttention via split-fp16 HMMA (mma.sync m16n8k16.f32.f16.f16.f32).
// out = softmax((x Wq^T * 0.06)(x Wk^T)^T)*dropmask @ (x Wv^T) @ Wo^T
// N = 8192, M = 1024.
// Precision: A fp16 hi-only; B split (Bh+Bl) on projections, QK^T, and the
// output GEMM. S@V runs SINGLE-PASS (V hi only): A=Sh is exact fp16, so the
// only added error is the dropped Vl term (~2.8e-4 relative on Y).
// R14 = R13 pipeline (validated) + templated SPLITB + mode-4 epilogue.
// ---------------------------------------------------------------------------

#define NF 8192
#define MF 1024

// ---------------- scratch (__device__ globals) ------------------------------
__device__ float  g_S [(size_t)NF * NF];                 // 256 MB logits
__device__ __half g_Sh[(size_t)NF * NF];                 // 128 MB (A side)
__device__ __half g_xh[(size_t)NF * MF];
__device__ __half g_Wkh[(size_t)MF * MF], g_Wkl[(size_t)MF * MF];
__device__ __half g_Wqh[(size_t)MF * MF], g_Wql[(size_t)MF * MF];
__device__ __half g_Wvh[(size_t)MF * MF], g_Wvl[(size_t)MF * MF];
__device__ __half g_Woh[(size_t)MF * MF], g_Wol[(size_t)MF * MF];
__device__ __half g_Kh[(size_t)NF * MF], g_Kl[(size_t)NF * MF];
__device__ __half g_Qh[(size_t)NF * MF];
__device__ __half g_Vth[(size_t)MF * NF];                // V^T hi only
__device__ __half g_Yh[(size_t)NF * MF];

// ---------------- tile config ----------------------------------------------
#define BM 128
#define BN 64
#define BKE 32                    // K elems per chunk (fp16)
#define RS 40                     // smem row stride in elems (80 B)
#define OFF_A  0                          // A: 128 rows x 80B = 10240
#define OFF_BH (BM * RS * 2)              // Bh: 64 rows x 80B = 5120
#define OFF_BL (BM * RS * 2 + BN * RS * 2)
#define STAGE_B ((BM + 2 * BN) * RS * 2)  // 20480
#define NSTAGE 3
#define DYN_SMEM (NSTAGE * STAGE_B)       // 61440/CTA (3 CTAs -> 180 KB/SM)

// ---------------- PTX helpers ----------------------------------------------
__device__ __forceinline__ uint32_t s2u(const void* p) {
    uint32_t a;
    asm("{ .reg .u64 t; cvta.to.shared.u64 t, %1; cvt.u32.u64 %0, t; }"
        : "=r"(a) : "l"(p));
    return a;
}
__device__ __forceinline__ void cpa16(uint32_t dst, const void* src) {
    asm volatile("cp.async.cg.shared.global [%0], [%1], 16;"
                 :: "r"(dst), "l"(src) : "memory");
}
__device__ __forceinline__ void ldsm4(uint32_t* r, uint32_t addr) {
    asm volatile("ldmatrix.sync.aligned.m8n8.x4.shared.b16 {%0,%1,%2,%3}, [%4];"
                 : "=r"(r[0]), "=r"(r[1]), "=r"(r[2]), "=r"(r[3]) : "r"(addr));
}
__device__ __forceinline__ void mma16816(float* c, const uint32_t* a,
                                         const uint32_t* b) {
    asm volatile(
        "mma.sync.aligned.m16n8k16.row.col.f32.f16.f16.f32 "
        "{%0,%1,%2,%3}, {%4,%5,%6,%7}, {%8,%9}, {%0,%1,%2,%3};"
        : "+f"(c[0]), "+f"(c[1]), "+f"(c[2]), "+f"(c[3])
        : "r"(a[0]), "r"(a[1]), "r"(a[2]), "r"(a[3]), "r"(b[0]), "r"(b[1]));
}
__device__ __forceinline__ void split2h(float v, __half& h, __half& l) {
    h = __float2half_rn(v);
    l = __float2half_rn(v - __half2float(h));
}

// ---------------------------------------------------------------------------
// NT GEMM: C[M,N] = alpha * Ah[M,K] * B[N,K]^T
//   SPLITB=true : B = Bh + Bl (2 MMA passes)
//   SPLITB=false: B = Bh only (1 MMA pass)
// mode 0: fp32 out. mode 1: split fp16 out. mode 3: fp16 hi-only out.
// mode 4: fp16 hi-only TRANSPOSED out (Ch[col*Mrows + row]).
// Requires M mult 128, N mult 64, K mult 32.
// ---------------------------------------------------------------------------
template <bool SPLITB>
__global__ __launch_bounds__(128, 3)
void gemm_mma(const __half* __restrict__ Ah,
              const __half* __restrict__ Bh, const __half* __restrict__ Bl,
              float* __restrict__ Cf,
              __half* __restrict__ Ch, __half* __restrict__ Cl,
              int Mrows, int Ncols, int Kdim, float alpha, int mode)
{
    extern __shared__ char dynraw[];
    const uint32_t sbase = s2u(dynraw);

    const int tid  = threadIdx.x;
    const int wid  = tid >> 5;
    const int lane = tid & 31;
    const int bx = blockIdx.x, by = blockIdx.y;

    const int wmBase = (wid & 1) * 64;      // warp M origin (0,64)
    const int wnBase = (wid >> 1) * 32;     // warp N origin (0,32)

    const size_t rowA0 = (size_t)by * BM;
    const size_t rowB0 = (size_t)bx * BN;

    auto load_chunk = [&](int kc, int stg) {
        const int k0 = kc * BKE;
        const uint32_t sb = sbase + stg * STAGE_B;
        #pragma unroll
        for (int i = 0; i < 4; i++) {                  // A: 512 x 16B
            const int idx = tid + i * 128;
            const int r = idx >> 2, c = idx & 3;
            const uint32_t so = (uint32_t)(r * RS * 2 + c * 16);
            cpa16(sb + OFF_A + so, Ah + (rowA0 + r) * (size_t)Kdim + k0 + c * 8);
        }
        #pragma unroll
        for (int i = 0; i < 2; i++) {                  // B: 256 x 16B each
            const int idx = tid + i * 128;
            const int r = idx >> 2, c = idx & 3;
            const uint32_t so = (uint32_t)(r * RS * 2 + c * 16);
            const size_t gb = (rowB0 + r) * (size_t)Kdim + k0 + c * 8;
            cpa16(sb + OFF_BH + so, Bh + gb);
            if (SPLITB) cpa16(sb + OFF_BL + so, Bl + gb);
        }
        asm volatile("cp.async.commit_group;" ::: "memory");
    };

    float acc[4][4][4];
    #pragma unroll
    for (int i = 0; i < 4; i++)
        #pragma unroll
        for (int j = 0; j < 4; j++)
            #pragma unroll
            for (int k = 0; k < 4; k++) acc[i][j][k] = 0.0f;

    const int nchunks = Kdim / BKE;

    const int q  = lane >> 3;
    const int r8 = lane & 7;
    const int aRowOff = ((q & 1) ? 8 : 0) + r8;
    const int aKOff   = ((q >> 1) ? 8 : 0);
    const int bRowOff = ((q >> 1) ? 8 : 0) + r8;
    const int bKOff   = ((q & 1) ? 8 : 0);

    // two fragment buffers: buf 0 <-> ks=0, buf 1 <-> ks=1
    uint32_t fa[2][4][4], fbh[2][2][4];
    uint32_t fbl[SPLITB ? 2 : 1][2][4];   // minimal footprint when unused

    auto ldfrag = [&](int buf, uint32_t sb, int ks) {
        #pragma unroll
        for (int am = 0; am < 4; am++) {
            const uint32_t off =
                (uint32_t)((wmBase + am * 16 + aRowOff) * RS
                           + ks * 16 + aKOff) * 2;
            ldsm4(fa[buf][am], sb + OFF_A + off);
        }
        #pragma unroll
        for (int j = 0; j < 2; j++) {
            const uint32_t off =
                (uint32_t)((wnBase + j * 16 + bRowOff) * RS
                           + ks * 16 + bKOff) * 2;
            ldsm4(fbh[buf][j], sb + OFF_BH + off);
            if (SPLITB) ldsm4(fbl[buf][j], sb + OFF_BL + off);
        }
    };
    auto do_mma = [&](int buf) {
        #pragma unroll
        for (int j = 0; j < 2; j++)
            #pragma unroll
            for (int am = 0; am < 4; am++) {
                mma16816(acc[am][j * 2],     fa[buf][am], fbh[buf][j]);
                mma16816(acc[am][j * 2 + 1], fa[buf][am], fbh[buf][j] + 2);
            }
        if (SPLITB) {
            #pragma unroll
            for (int j = 0; j < 2; j++)
                #pragma unroll
                for (int am = 0; am < 4; am++) {
                    mma16816(acc[am][j * 2],     fa[buf][am], fbl[buf][j]);
                    mma16816(acc[am][j * 2 + 1], fa[buf][am], fbl[buf][j] + 2);
                }
        }
    };

    // prologue: stages 0,1 in flight; chunk 0 globally resident; frag ks0 in
    load_chunk(0, 0);
    if (nchunks > 1) {
        load_chunk(1, 1);
        asm volatile("cp.async.wait_group 1;" ::: "memory");  // own chunk0
    } else {
        asm volatile("cp.async.wait_group 0;" ::: "memory");
    }
    __syncthreads();                                            // ALL chunk0
    ldfrag(0, sbase, 0);

    // invariant at top of iter kc: chunk kc resident globally; buf0 = (kc,ks0)
    for (int kc = 0; kc < nchunks; kc++) {
        const uint32_t sb_cur = sbase + (kc % NSTAGE) * STAGE_B;
        const uint32_t sb_nxt = sbase + ((kc + 1) % NSTAGE) * STAGE_B;

        // phase A: prefetch (kc, ks1) under MMA of (kc, ks0)
        ldfrag(1, sb_cur, 1);
        do_mma(0);

        if (kc + 2 < nchunks) {
            load_chunk(kc + 2, (kc + 2) % NSTAGE);
            asm volatile("cp.async.wait_group 1;" ::: "memory");
        } else {
            asm volatile("cp.async.wait_group 0;" ::: "memory");
        }
        __syncthreads();   // chunk kc+1 resident for ALL warps

        // phase B: prefetch (kc+1, ks0) under MMA of (kc, ks1)
        if (kc + 1 < nchunks) ldfrag(0, sb_nxt, 0);
        do_mma(1);
    }

    // ---------------- epilogue --------------------------------------------
    #pragma unroll
    for (int am = 0; am < 4; am++) {
        const int r0 = by * BM + wmBase + am * 16 + (lane >> 2);
        #pragma unroll
        for (int an = 0; an < 4; an++) {
            const int c0 = bx * BN + wnBase + an * 8 + (lane & 3) * 2;
            const float v00 = alpha * acc[am][an][0];
            const float v01 = alpha * acc[am][an][1];
            const float v10 = alpha * acc[am][an][2];
            const float v11 = alpha * acc[am][an][3];
            if (mode == 0) {
                *(float2*)(Cf + (size_t)r0 * Ncols + c0)       = make_float2(v00, v01);
                *(float2*)(Cf + (size_t)(r0 + 8) * Ncols + c0) = make_float2(v10, v11);
            } else if (mode == 1) {
                __half h0, l0, h1, l1;
                split2h(v00, h0, l0); split2h(v01, h1, l1);
                *(__half2*)(Ch + (size_t)r0 * Ncols + c0) = __halves2half2(h0, h1);
                *(__half2*)(Cl + (size_t)r0 * Ncols + c0) = __halves2half2(l0, l1);
                split2h(v10, h0, l0); split2h(v11, h1, l1);
                *(__half2*)(Ch + (size_t)(r0 + 8) * Ncols + c0) = __halves2half2(h0, h1);
                *(__half2*)(Cl + (size_t)(r0 + 8) * Ncols + c0) = __halves2half2(l0, l1);
            } else if (mode == 3) {          // fp16 hi only, row-major
                *(__half2*)(Ch + (size_t)r0 * Ncols + c0) =
                    __halves2half2(__float2half_rn(v00), __float2half_rn(v01));
                *(__half2*)(Ch + (size_t)(r0 + 8) * Ncols + c0) =
                    __halves2half2(__float2half_rn(v10), __float2half_rn(v11));
            } else {                         // mode 4: fp16 hi only, transposed
                Ch[(size_t)c0 * Mrows + r0]           = __float2half_rn(v00);
                Ch[(size_t)(c0 + 1) * Mrows + r0]     = __float2half_rn(v01);
                Ch[(size_t)c0 * Mrows + r0 + 8]       = __float2half_rn(v10);
                Ch[(size_t)(c0 + 1) * Mrows + r0 + 8] = __float2half_rn(v11);
            }
        }
    }
}

// ---------------------------------------------------------------------------
// fp32 -> fp16 cast (A-side tensors)
// ---------------------------------------------------------------------------
__global__ __launch_bounds__(256)
void cast_f32_f16(const float* __restrict__ x, __half* __restrict__ h, size_t n)
{
    size_t i = (size_t)blockIdx.x * 256 + threadIdx.x;
    size_t stride = (size_t)gridDim.x * 256;
    for (; i < n; i += stride) h[i] = __float2half_rn(x[i]);
}

// fused (hi,lo) split of the four MFxMF weight matrices
__global__ __launch_bounds__(256)
void split_w4(const float* __restrict__ w0, __half* __restrict__ h0, __half* __restrict__ l0,
              const float* __restrict__ w1, __half* __restrict__ h1, __half* __restrict__ l1,
              const float* __restrict__ w2, __half* __restrict__ h2, __half* __restrict__ l2,
              const float* __restrict__ w3, __half* __restrict__ h3, __half* __restrict__ l3)
{
    const size_t n = (size_t)MF * MF;
    size_t i = (size_t)blockIdx.x * 256 + threadIdx.x;
    size_t stride = (size_t)gridDim.x * 256;
    for (; i < n; i += stride) {
        float v; __half hb, lb;
        v = w0[i]; split2h(v, hb, lb); h0[i] = hb; l0[i] = lb;
        v = w1[i]; split2h(v, hb, lb); h1[i] = hb; l1[i] = lb;
        v = w2[i]; split2h(v, hb, lb); h2[i] = hb; l2[i] = lb;
        v = w3[i]; split2h(v, hb, lb); h3[i] = hb; l3[i] = lb;
    }
}

// ---------------------------------------------------------------------------
// Row softmax + dropout mask -> fp16  (MUST run with SMX_T threads)
// ---------------------------------------------------------------------------
#define SMX_T 256
__global__ __launch_bounds__(SMX_T)
void softmax_dropout_h(const float* __restrict__ S, const float* __restrict__ u,
                       __half* __restrict__ Sh)
{
    __shared__ float row[NF];
    __shared__ float red[SMX_T];

    const int r = blockIdx.x;
    const int tid = threadIdx.x;
    const float* Srow = S + (size_t)r * NF;
    const float* urow = u + (size_t)r * NF;
    const size_t base = (size_t)r * NF;

    float lmax = -INFINITY;
    for (int c = tid; c < NF; c += SMX_T) {
        float v = Srow[c];
        row[c] = v;
        lmax = fmaxf(lmax, v);
    }
    red[tid] = lmax;
    __syncthreads();
    #pragma unroll
    for (int s = SMX_T / 2; s > 0; s >>= 1) {
        if (tid < s) red[tid] = fmaxf(red[tid], red[tid + s]);
        __syncthreads();
    }
    const float m = red[0];
    __syncthreads();

    float lsum = 0.0f;
    for (int c = tid; c < NF; c += SMX_T) {
        float e = __expf(row[c] - m);
        row[c] = e;
        lsum += e;
    }
    red[tid] = lsum;
    __syncthreads();
    #pragma unroll
    for (int s = SMX_T / 2; s > 0; s >>= 1) {
        if (tid < s) red[tid] += red[tid + s];
        __syncthreads();
    }
    const float inv = 1.0f / red[0];

    for (int c = tid; c < NF; c += SMX_T) {
        float keep = (urow[c] >= 0.5f) ? 2.0f : 0.0f;
        Sh[base + c] = __float2half_rn(row[c] * inv * keep);
    }
}

// ---------------------------------------------------------------------------
// Launch
// ---------------------------------------------------------------------------
extern "C" void kernel_launch(void* const* d_in, const int* in_sizes, int n_in,
                              void* d_out, int out_size)
{
    const float* x  = (const float*)d_in[0];
    const float* Wk = (const float*)d_in[1];
    const float* Wq = (const float*)d_in[2];
    const float* Wv = (const float*)d_in[3];
    const float* Wo = (const float*)d_in[4];
    const float* u  = (const float*)d_in[5];
    float* out = (float*)d_out;

    cudaFuncSetAttribute(gemm_mma<true>,
                         cudaFuncAttributeMaxDynamicSharedMemorySize, DYN_SMEM);
    cudaFuncSetAttribute(gemm_mma<false>,
                         cudaFuncAttributeMaxDynamicSharedMemorySize, DYN_SMEM);

    float* S;
    __half *xh, *Wkh, *Wkl, *Wqh, *Wql, *Wvh, *Wvl, *Woh, *Wol;
    __half *Kh, *Kl, *Qh, *Vth, *Sh, *Yh;
    cudaGetSymbolAddress((void**)&S, g_S);
    cudaGetSymbolAddress((void**)&xh, g_xh);
    cudaGetSymbolAddress((void**)&Wkh, g_Wkh); cudaGetSymbolAddress((void**)&Wkl, g_Wkl);
    cudaGetSymbolAddress((void**)&Wqh, g_Wqh); cudaGetSymbolAddress((void**)&Wql, g_Wql);
    cudaGetSymbolAddress((void**)&Wvh, g_Wvh); cudaGetSymbolAddress((void**)&Wvl, g_Wvl);
    cudaGetSymbolAddress((void**)&Woh, g_Woh); cudaGetSymbolAddress((void**)&Wol, g_Wol);
    cudaGetSymbolAddress((void**)&Kh, g_Kh);   cudaGetSymbolAddress((void**)&Kl, g_Kl);
    cudaGetSymbolAddress((void**)&Qh, g_Qh);
    cudaGetSymbolAddress((void**)&Vth, g_Vth);
    cudaGetSymbolAddress((void**)&Sh, g_Sh);
    cudaGetSymbolAddress((void**)&Yh, g_Yh);

    // 1) conversions
    cast_f32_f16<<<4096, 256>>>(x, xh, (size_t)NF * MF);             // launch 0
    split_w4<<<1024, 256>>>(Wk, Wkh, Wkl, Wq, Wqh, Wql,
                            Wv, Wvh, Wvl, Wo, Woh, Wol);             // launch 1

    const dim3 gemmBlk(128);
    const dim3 gProj(MF / BN, NF / BM);   // (16, 64)
    const dim3 gAttn(NF / BN, NF / BM);   // (128, 64)

    // 2) projections
    gemm_mma<true><<<gProj, gemmBlk, DYN_SMEM>>>(xh, Wkh, Wkl, nullptr, Kh, Kl,
                                                 NF, MF, MF, 1.0f, 1);
    gemm_mma<true><<<gProj, gemmBlk, DYN_SMEM>>>(xh, Wqh, Wql, nullptr, Qh, nullptr,
                                                 NF, MF, MF, 0.06f, 3);
    gemm_mma<true><<<gProj, gemmBlk, DYN_SMEM>>>(xh, Wvh, Wvl, nullptr, Vth, nullptr,
                                                 NF, MF, MF, 1.0f, 4);

    // 3) logits S = Q K^T (fp32) — launch 5 for ncu (big GEMM, 2-pass)
    gemm_mma<true><<<gAttn, gemmBlk, DYN_SMEM>>>(Qh, Kh, Kl, S, nullptr, nullptr,
                                                 NF, NF, MF, 1.0f, 0);

    // 4) softmax + dropout -> fp16
    softmax_dropout_h<<<NF, SMX_T>>>(S, u, Sh);

    // 5) Y = W V — SINGLE-PASS (A = Sh exact fp16, B = Vth hi only)
    gemm_mma<false><<<gProj, gemmBlk, DYN_SMEM>>>(Sh, Vth, nullptr, nullptr, Yh, nullptr,
                                                  NF, MF, NF, 1.0f, 3);

    // 6) out = Y Wo^T (fp32, 2-pass)
    gemm_mma<true><<<gProj, gemmBlk, DYN_SMEM>>>(Yh, Woh, Wol, out, nullptr, nullptr,
                                                 NF, MF, MF, 1.0f, 0);
}

// round 15
// speedup vs baseline: 5.7285x; 1.1144x over previous
#include <cuda_runtime.h>
#include <cuda_fp16.h>
#include <cstdint>
#include <math.h>

// ---------------------------------------------------------------------------
// SelfAttention via split-fp16 HMMA (mma.sync m16n8k16.f32.f16.f16.f32).
// out = softmax((x Wq^T * 0.06)(x Wk^T)^T)*dropmask @ (x Wv^T) @ Wo^T
// N = 8192, M = 1024.
// Precision scheme (calibrated over R8..R14):
//   - A operands always fp16 hi-only.
//   - Projections (Wk,Wq,Wv) and output GEMM (Wo): B split hi+lo, 2 passes.
//   - QK^T: single-pass (Kl dropped) — softmax sensitivity makes the logit
//     perturbation ~1e-4 absolute (Q carries the 0.06 scale).
//   - S@V: single-pass (Vl dropped) — Sh is exact fp16.
// R15 = R14 + single-pass QK^T + K projection emits hi-only.
// ---------------------------------------------------------------------------

#define NF 8192
#define MF 1024

// ---------------- scratch (__device__ globals) ------------------------------
__device__ float  g_S [(size_t)NF * NF];                 // 256 MB logits
__device__ __half g_Sh[(size_t)NF * NF];                 // 128 MB (A side)
__device__ __half g_xh[(size_t)NF * MF];
__device__ __half g_Wkh[(size_t)MF * MF], g_Wkl[(size_t)MF * MF];
__device__ __half g_Wqh[(size_t)MF * MF], g_Wql[(size_t)MF * MF];
__device__ __half g_Wvh[(size_t)MF * MF], g_Wvl[(size_t)MF * MF];
__device__ __half g_Woh[(size_t)MF * MF], g_Wol[(size_t)MF * MF];
__device__ __half g_Kh[(size_t)NF * MF];                 // K hi only
__device__ __half g_Qh[(size_t)NF * MF];
__device__ __half g_Vth[(size_t)MF * NF];                // V^T hi only
__device__ __half g_Yh[(size_t)NF * MF];

// ---------------- tile config ----------------------------------------------
#define BM 128
#define BN 64
#define BKE 32                    // K elems per chunk (fp16)
#define RS 40                     // smem row stride in elems (80 B)
#define OFF_A  0                          // A: 128 rows x 80B = 10240
#define OFF_BH (BM * RS * 2)              // Bh: 64 rows x 80B = 5120
#define OFF_BL (BM * RS * 2 + BN * RS * 2)
#define STAGE_B ((BM + 2 * BN) * RS * 2)  // 20480
#define NSTAGE 3
#define DYN_SMEM (NSTAGE * STAGE_B)       // 61440/CTA (3 CTAs -> 180 KB/SM)

// ---------------- PTX helpers ----------------------------------------------
__device__ __forceinline__ uint32_t s2u(const void* p) {
    uint32_t a;
    asm("{ .reg .u64 t; cvta.to.shared.u64 t, %1; cvt.u32.u64 %0, t; }"
        : "=r"(a) : "l"(p));
    return a;
}
__device__ __forceinline__ void cpa16(uint32_t dst, const void* src) {
    asm volatile("cp.async.cg.shared.global [%0], [%1], 16;"
                 :: "r"(dst), "l"(src) : "memory");
}
__device__ __forceinline__ void ldsm4(uint32_t* r, uint32_t addr) {
    asm volatile("ldmatrix.sync.aligned.m8n8.x4.shared.b16 {%0,%1,%2,%3}, [%4];"
                 : "=r"(r[0]), "=r"(r[1]), "=r"(r[2]), "=r"(r[3]) : "r"(addr));
}
__device__ __forceinline__ void mma16816(float* c, const uint32_t* a,
                                         const uint32_t* b) {
    asm volatile(
        "mma.sync.aligned.m16n8k16.row.col.f32.f16.f16.f32 "
        "{%0,%1,%2,%3}, {%4,%5,%6,%7}, {%8,%9}, {%0,%1,%2,%3};"
        : "+f"(c[0]), "+f"(c[1]), "+f"(c[2]), "+f"(c[3])
        : "r"(a[0]), "r"(a[1]), "r"(a[2]), "r"(a[3]), "r"(b[0]), "r"(b[1]));
}
__device__ __forceinline__ void split2h(float v, __half& h, __half& l) {
    h = __float2half_rn(v);
    l = __float2half_rn(v - __half2float(h));
}

// ---------------------------------------------------------------------------
// NT GEMM: C[M,N] = alpha * Ah[M,K] * B[N,K]^T
//   SPLITB=true : B = Bh + Bl (2 MMA passes)
//   SPLITB=false: B = Bh only (1 MMA pass)
// mode 0: fp32 out. mode 1: split fp16 out. mode 3: fp16 hi-only out.
// mode 4: fp16 hi-only TRANSPOSED out (Ch[col*Mrows + row]).
// Requires M mult 128, N mult 64, K mult 32.
// ---------------------------------------------------------------------------
template <bool SPLITB>
__global__ __launch_bounds__(128, 3)
void gemm_mma(const __half* __restrict__ Ah,
              const __half* __restrict__ Bh, const __half* __restrict__ Bl,
              float* __restrict__ Cf,
              __half* __restrict__ Ch, __half* __restrict__ Cl,
              int Mrows, int Ncols, int Kdim, float alpha, int mode)
{
    extern __shared__ char dynraw[];
    const uint32_t sbase = s2u(dynraw);

    const int tid  = threadIdx.x;
    const int wid  = tid >> 5;
    const int lane = tid & 31;
    const int bx = blockIdx.x, by = blockIdx.y;

    const int wmBase = (wid & 1) * 64;      // warp M origin (0,64)
    const int wnBase = (wid >> 1) * 32;     // warp N origin (0,32)

    const size_t rowA0 = (size_t)by * BM;
    const size_t rowB0 = (size_t)bx * BN;

    auto load_chunk = [&](int kc, int stg) {
        const int k0 = kc * BKE;
        const uint32_t sb = sbase + stg * STAGE_B;
        #pragma unroll
        for (int i = 0; i < 4; i++) {                  // A: 512 x 16B
            const int idx = tid + i * 128;
            const int r = idx >> 2, c = idx & 3;
            const uint32_t so = (uint32_t)(r * RS * 2 + c * 16);
            cpa16(sb + OFF_A + so, Ah + (rowA0 + r) * (size_t)Kdim + k0 + c * 8);
        }
        #pragma unroll
        for (int i = 0; i < 2; i++) {                  // B: 256 x 16B each
            const int idx = tid + i * 128;
            const int r = idx >> 2, c = idx & 3;
            const uint32_t so = (uint32_t)(r * RS * 2 + c * 16);
            const size_t gb = (rowB0 + r) * (size_t)Kdim + k0 + c * 8;
            cpa16(sb + OFF_BH + so, Bh + gb);
            if (SPLITB) cpa16(sb + OFF_BL + so, Bl + gb);
        }
        asm volatile("cp.async.commit_group;" ::: "memory");
    };

    float acc[4][4][4];
    #pragma unroll
    for (int i = 0; i < 4; i++)
        #pragma unroll
        for (int j = 0; j < 4; j++)
            #pragma unroll
            for (int k = 0; k < 4; k++) acc[i][j][k] = 0.0f;

    const int nchunks = Kdim / BKE;

    const int q  = lane >> 3;
    const int r8 = lane & 7;
    const int aRowOff = ((q & 1) ? 8 : 0) + r8;
    const int aKOff   = ((q >> 1) ? 8 : 0);
    const int bRowOff = ((q >> 1) ? 8 : 0) + r8;
    const int bKOff   = ((q & 1) ? 8 : 0);

    // two fragment buffers: buf 0 <-> ks=0, buf 1 <-> ks=1
    uint32_t fa[2][4][4], fbh[2][2][4];
    uint32_t fbl[SPLITB ? 2 : 1][2][4];

    auto ldfrag = [&](int buf, uint32_t sb, int ks) {
        #pragma unroll
        for (int am = 0; am < 4; am++) {
            const uint32_t off =
                (uint32_t)((wmBase + am * 16 + aRowOff) * RS
                           + ks * 16 + aKOff) * 2;
            ldsm4(fa[buf][am], sb + OFF_A + off);
        }
        #pragma unroll
        for (int j = 0; j < 2; j++) {
            const uint32_t off =
                (uint32_t)((wnBase + j * 16 + bRowOff) * RS
                           + ks * 16 + bKOff) * 2;
            ldsm4(fbh[buf][j], sb + OFF_BH + off);
            if (SPLITB) ldsm4(fbl[buf][j], sb + OFF_BL + off);
        }
    };
    auto do_mma = [&](int buf) {
        #pragma unroll
        for (int j = 0; j < 2; j++)
            #pragma unroll
            for (int am = 0; am < 4; am++) {
                mma16816(acc[am][j * 2],     fa[buf][am], fbh[buf][j]);
                mma16816(acc[am][j * 2 + 1], fa[buf][am], fbh[buf][j] + 2);
            }
        if (SPLITB) {
            #pragma unroll
            for (int j = 0; j < 2; j++)
                #pragma unroll
                for (int am = 0; am < 4; am++) {
                    mma16816(acc[am][j * 2],     fa[buf][am], fbl[buf][j]);
                    mma16816(acc[am][j * 2 + 1], fa[buf][am], fbl[buf][j] + 2);
                }
        }
    };

    // prologue: stages 0,1 in flight; chunk 0 globally resident; frag ks0 in
    load_chunk(0, 0);
    if (nchunks > 1) {
        load_chunk(1, 1);
        asm volatile("cp.async.wait_group 1;" ::: "memory");  // own chunk0
    } else {
        asm volatile("cp.async.wait_group 0;" ::: "memory");
    }
    __syncthreads();                                            // ALL chunk0
    ldfrag(0, sbase, 0);

    // invariant at top of iter kc: chunk kc resident globally; buf0 = (kc,ks0)
    for (int kc = 0; kc < nchunks; kc++) {
        const uint32_t sb_cur = sbase + (kc % NSTAGE) * STAGE_B;
        const uint32_t sb_nxt = sbase + ((kc + 1) % NSTAGE) * STAGE_B;

        // phase A: prefetch (kc, ks1) under MMA of (kc, ks0)
        ldfrag(1, sb_cur, 1);
        do_mma(0);

        if (kc + 2 < nchunks) {
            load_chunk(kc + 2, (kc + 2) % NSTAGE);
            asm volatile("cp.async.wait_group 1;" ::: "memory");
        } else {
            asm volatile("cp.async.wait_group 0;" ::: "memory");
        }
        __syncthreads();   // chunk kc+1 resident for ALL warps

        // phase B: prefetch (kc+1, ks0) under MMA of (kc, ks1)
        if (kc + 1 < nchunks) ldfrag(0, sb_nxt, 0);
        do_mma(1);
    }

    // ---------------- epilogue --------------------------------------------
    #pragma unroll
    for (int am = 0; am < 4; am++) {
        const int r0 = by * BM + wmBase + am * 16 + (lane >> 2);
        #pragma unroll
        for (int an = 0; an < 4; an++) {
            const int c0 = bx * BN + wnBase + an * 8 + (lane & 3) * 2;
            const float v00 = alpha * acc[am][an][0];
            const float v01 = alpha * acc[am][an][1];
            const float v10 = alpha * acc[am][an][2];
            const float v11 = alpha * acc[am][an][3];
            if (mode == 0) {
                *(float2*)(Cf + (size_t)r0 * Ncols + c0)       = make_float2(v00, v01);
                *(float2*)(Cf + (size_t)(r0 + 8) * Ncols + c0) = make_float2(v10, v11);
            } else if (mode == 1) {
                __half h0, l0, h1, l1;
                split2h(v00, h0, l0); split2h(v01, h1, l1);
                *(__half2*)(Ch + (size_t)r0 * Ncols + c0) = __halves2half2(h0, h1);
                *(__half2*)(Cl + (size_t)r0 * Ncols + c0) = __halves2half2(l0, l1);
                split2h(v10, h0, l0); split2h(v11, h1, l1);
                *(__half2*)(Ch + (size_t)(r0 + 8) * Ncols + c0) = __halves2half2(h0, h1);
                *(__half2*)(Cl + (size_t)(r0 + 8) * Ncols + c0) = __halves2half2(l0, l1);
            } else if (mode == 3) {          // fp16 hi only, row-major
                *(__half2*)(Ch + (size_t)r0 * Ncols + c0) =
                    __halves2half2(__float2half_rn(v00), __float2half_rn(v01));
                *(__half2*)(Ch + (size_t)(r0 + 8) * Ncols + c0) =
                    __halves2half2(__float2half_rn(v10), __float2half_rn(v11));
            } else {                         // mode 4: fp16 hi only, transposed
                Ch[(size_t)c0 * Mrows + r0]           = __float2half_rn(v00);
                Ch[(size_t)(c0 + 1) * Mrows + r0]     = __float2half_rn(v01);
                Ch[(size_t)c0 * Mrows + r0 + 8]       = __float2half_rn(v10);
                Ch[(size_t)(c0 + 1) * Mrows + r0 + 8] = __float2half_rn(v11);
            }
        }
    }
}

// ---------------------------------------------------------------------------
// fp32 -> fp16 cast (A-side tensors)
// ---------------------------------------------------------------------------
__global__ __launch_bounds__(256)
void cast_f32_f16(const float* __restrict__ x, __half* __restrict__ h, size_t n)
{
    size_t i = (size_t)blockIdx.x * 256 + threadIdx.x;
    size_t stride = (size_t)gridDim.x * 256;
    for (; i < n; i += stride) h[i] = __float2half_rn(x[i]);
}

// fused (hi,lo) split of the four MFxMF weight matrices
__global__ __launch_bounds__(256)
void split_w4(const float* __restrict__ w0, __half* __restrict__ h0, __half* __restrict__ l0,
              const float* __restrict__ w1, __half* __restrict__ h1, __half* __restrict__ l1,
              const float* __restrict__ w2, __half* __restrict__ h2, __half* __restrict__ l2,
              const float* __restrict__ w3, __half* __restrict__ h3, __half* __restrict__ l3)
{
    const size_t n = (size_t)MF * MF;
    size_t i = (size_t)blockIdx.x * 256 + threadIdx.x;
    size_t stride = (size_t)gridDim.x * 256;
    for (; i < n; i += stride) {
        float v; __half hb, lb;
        v = w0[i]; split2h(v, hb, lb); h0[i] = hb; l0[i] = lb;
        v = w1[i]; split2h(v, hb, lb); h1[i] = hb; l1[i] = lb;
        v = w2[i]; split2h(v, hb, lb); h2[i] = hb; l2[i] = lb;
        v = w3[i]; split2h(v, hb, lb); h3[i] = hb; l3[i] = lb;
    }
}

// ---------------------------------------------------------------------------
// Row softmax + dropout mask -> fp16  (MUST run with SMX_T threads)
// ---------------------------------------------------------------------------
#define SMX_T 256
__global__ __launch_bounds__(SMX_T)
void softmax_dropout_h(const float* __restrict__ S, const float* __restrict__ u,
                       __half* __restrict__ Sh)
{
    __shared__ float row[NF];
    __shared__ float red[SMX_T];

    const int r = blockIdx.x;
    const int tid = threadIdx.x;
    const float* Srow = S + (size_t)r * NF;
    const float* urow = u + (size_t)r * NF;
    const size_t base = (size_t)r * NF;

    float lmax = -INFINITY;
    for (int c = tid; c < NF; c += SMX_T) {
        float v = Srow[c];
        row[c] = v;
        lmax = fmaxf(lmax, v);
    }
    red[tid] = lmax;
    __syncthreads();
    #pragma unroll
    for (int s = SMX_T / 2; s > 0; s >>= 1) {
        if (tid < s) red[tid] = fmaxf(red[tid], red[tid + s]);
        __syncthreads();
    }
    const float m = red[0];
    __syncthreads();

    float lsum = 0.0f;
    for (int c = tid; c < NF; c += SMX_T) {
        float e = __expf(row[c] - m);
        row[c] = e;
        lsum += e;
    }
    red[tid] = lsum;
    __syncthreads();
    #pragma unroll
    for (int s = SMX_T / 2; s > 0; s >>= 1) {
        if (tid < s) red[tid] += red[tid + s];
        __syncthreads();
    }
    const float inv = 1.0f / red[0];

    for (int c = tid; c < NF; c += SMX_T) {
        float keep = (urow[c] >= 0.5f) ? 2.0f : 0.0f;
        Sh[base + c] = __float2half_rn(row[c] * inv * keep);
    }
}

// ---------------------------------------------------------------------------
// Launch
// ---------------------------------------------------------------------------
extern "C" void kernel_launch(void* const* d_in, const int* in_sizes, int n_in,
                              void* d_out, int out_size)
{
    const float* x  = (const float*)d_in[0];
    const float* Wk = (const float*)d_in[1];
    const float* Wq = (const float*)d_in[2];
    const float* Wv = (const float*)d_in[3];
    const float* Wo = (const float*)d_in[4];
    const float* u  = (const float*)d_in[5];
    float* out = (float*)d_out;

    cudaFuncSetAttribute(gemm_mma<true>,
                         cudaFuncAttributeMaxDynamicSharedMemorySize, DYN_SMEM);
    cudaFuncSetAttribute(gemm_mma<false>,
                         cudaFuncAttributeMaxDynamicSharedMemorySize, DYN_SMEM);

    float* S;
    __half *xh, *Wkh, *Wkl, *Wqh, *Wql, *Wvh, *Wvl, *Woh, *Wol;
    __half *Kh, *Qh, *Vth, *Sh, *Yh;
    cudaGetSymbolAddress((void**)&S, g_S);
    cudaGetSymbolAddress((void**)&xh, g_xh);
    cudaGetSymbolAddress((void**)&Wkh, g_Wkh); cudaGetSymbolAddress((void**)&Wkl, g_Wkl);
    cudaGetSymbolAddress((void**)&Wqh, g_Wqh); cudaGetSymbolAddress((void**)&Wql, g_Wql);
    cudaGetSymbolAddress((void**)&Wvh, g_Wvh); cudaGetSymbolAddress((void**)&Wvl, g_Wvl);
    cudaGetSymbolAddress((void**)&Woh, g_Woh); cudaGetSymbolAddress((void**)&Wol, g_Wol);
    cudaGetSymbolAddress((void**)&Kh, g_Kh);
    cudaGetSymbolAddress((void**)&Qh, g_Qh);
    cudaGetSymbolAddress((void**)&Vth, g_Vth);
    cudaGetSymbolAddress((void**)&Sh, g_Sh);
    cudaGetSymbolAddress((void**)&Yh, g_Yh);

    // 1) conversions
    cast_f32_f16<<<4096, 256>>>(x, xh, (size_t)NF * MF);             // launch 0
    split_w4<<<1024, 256>>>(Wk, Wkh, Wkl, Wq, Wqh, Wql,
                            Wv, Wvh, Wvl, Wo, Woh, Wol);             // launch 1

    const dim3 gemmBlk(128);
    const dim3 gProj(MF / BN, NF / BM);   // (16, 64)
    const dim3 gAttn(NF / BN, NF / BM);   // (128, 64)

    // 2) projections (K and V emit hi-only; Q hi-only)
    gemm_mma<true><<<gProj, gemmBlk, DYN_SMEM>>>(xh, Wkh, Wkl, nullptr, Kh, nullptr,
                                                 NF, MF, MF, 1.0f, 3);
    gemm_mma<true><<<gProj, gemmBlk, DYN_SMEM>>>(xh, Wqh, Wql, nullptr, Qh, nullptr,
                                                 NF, MF, MF, 0.06f, 3);
    gemm_mma<true><<<gProj, gemmBlk, DYN_SMEM>>>(xh, Wvh, Wvl, nullptr, Vth, nullptr,
                                                 NF, MF, MF, 1.0f, 4);

    // 3) logits S = Q K^T (fp32) — SINGLE-PASS (Kl dropped); launch 5 for ncu
    gemm_mma<false><<<gAttn, gemmBlk, DYN_SMEM>>>(Qh, Kh, nullptr, S, nullptr, nullptr,
                                                  NF, NF, MF, 1.0f, 0);

    // 4) softmax + dropout -> fp16
    softmax_dropout_h<<<NF, SMX_T>>>(S, u, Sh);

    // 5) Y = W V — SINGLE-PASS (A = Sh exact fp16, B = Vth hi only)
    gemm_mma<false><<<gProj, gemmBlk, DYN_SMEM>>>(Sh, Vth, nullptr, nullptr, Yh, nullptr,
                                                  NF, MF, NF, 1.0f, 3);

    // 6) out = Y Wo^T (fp32, 2-pass — keep error headroom)
    gemm_mma<true><<<gProj, gemmBlk, DYN_SMEM>>>(Yh, Woh, Wol, out, nullptr, nullptr,
                                                 NF, MF, MF, 1.0f, 0);
}